// round 5
// baseline (speedup 1.0000x reference)
#include <cuda_runtime.h>
#include <math.h>
#include <stdint.h>

#define CD   1024
#define CH   16
#define CFF  4096
#define CB   8
#define CN   1024
#define NTOK (CB*CN)   // 8192

// ---------------- scratch (no allocations allowed) ----------------
__device__ float g_xn [NTOK*CD];      // layernorm1(x), tf32-rounded
__device__ float g_qkv[NTOK*3*CD];    // qkv projection
__device__ float g_ao [NTOK*CD];      // attention output, tf32-rounded
__device__ float g_x1 [NTOK*CD];      // attn + residual
__device__ float g_x2 [NTOK*CD];      // layernorm2(x1), tf32-rounded
__device__ float g_h  [NTOK*CFF];     // gelu(lin1), tf32-rounded
__device__ float g_wq [3*CD*CD];      // tf32-rounded weights
__device__ float g_wo [CD*CD];
__device__ float g_w1 [CFF*CD];
__device__ float g_w2 [CD*CFF];

// ---------------- helpers ----------------
__device__ __forceinline__ uint32_t smem_u32(const void* p) {
    uint32_t a;
    asm("{ .reg .u64 t; cvta.to.shared.u64 t, %1; cvt.u32.u64 %0, t; }" : "=r"(a) : "l"(p));
    return a;
}
__device__ __forceinline__ float to_tf32(float x) {
    uint32_t u;
    asm("cvt.rna.tf32.f32 %0, %1;" : "=r"(u) : "f"(x));
    return __uint_as_float(u);
}
__device__ __forceinline__ void mma_tf32(float* d, const uint32_t* a, const uint32_t* b) {
    asm volatile(
        "mma.sync.aligned.m16n8k8.row.col.f32.tf32.tf32.f32 "
        "{%0,%1,%2,%3},{%4,%5,%6,%7},{%8,%9},{%0,%1,%2,%3};"
        : "+f"(d[0]), "+f"(d[1]), "+f"(d[2]), "+f"(d[3])
        : "r"(a[0]), "r"(a[1]), "r"(a[2]), "r"(a[3]), "r"(b[0]), "r"(b[1]));
}
__device__ __forceinline__ void ldsm_x4(uint32_t* r, uint32_t addr) {
    asm volatile("ldmatrix.sync.aligned.m8n8.x4.shared.b16 {%0,%1,%2,%3}, [%4];"
        : "=r"(r[0]), "=r"(r[1]), "=r"(r[2]), "=r"(r[3]) : "r"(addr));
}

// ---------------- tf32 RN rounding copy (weights) ----------------
__global__ void round_tf32_k(const float4* __restrict__ src, float4* __restrict__ dst, int n4) {
    int i = blockIdx.x * blockDim.x + threadIdx.x;
    if (i < n4) {
        float4 v = src[i];
        v.x = to_tf32(v.x); v.y = to_tf32(v.y); v.z = to_tf32(v.z); v.w = to_tf32(v.w);
        dst[i] = v;
    }
}

// ---------------- LayerNorm (output rounded to tf32) ----------------
__global__ void __launch_bounds__(256) layernorm_k(
    const float* __restrict__ x, const float* __restrict__ w,
    const float* __restrict__ b, float* __restrict__ y)
{
    int row = blockIdx.x;
    int tid = threadIdx.x;
    const float4* xr = (const float4*)(x + (size_t)row * CD);
    float4 xv = xr[tid];
    float s  = xv.x + xv.y + xv.z + xv.w;
    float ss = xv.x*xv.x + xv.y*xv.y + xv.z*xv.z + xv.w*xv.w;
    #pragma unroll
    for (int o = 16; o; o >>= 1) {
        s  += __shfl_xor_sync(0xffffffffu, s,  o);
        ss += __shfl_xor_sync(0xffffffffu, ss, o);
    }
    __shared__ float sm1[8], sm2[8];
    if ((tid & 31) == 0) { sm1[tid >> 5] = s; sm2[tid >> 5] = ss; }
    __syncthreads();
    float ts = 0.f, tss = 0.f;
    #pragma unroll
    for (int i = 0; i < 8; i++) { ts += sm1[i]; tss += sm2[i]; }
    float mu   = ts * (1.0f / CD);
    float var  = tss * (1.0f / CD) - mu * mu;
    float rstd = rsqrtf(var + 1e-5f);
    float4 wv = ((const float4*)w)[tid];
    float4 bv = ((const float4*)b)[tid];
    float4 ov;
    ov.x = to_tf32((xv.x - mu) * rstd * wv.x + bv.x);
    ov.y = to_tf32((xv.y - mu) * rstd * wv.y + bv.y);
    ov.z = to_tf32((xv.z - mu) * rstd * wv.z + bv.z);
    ov.w = to_tf32((xv.w - mu) * rstd * wv.w + bv.w);
    ((float4*)(y + (size_t)row * CD))[tid] = ov;
}

// ---------------- tf32 mma.sync NT GEMM (ldmatrix + K-chunk 64) ----------------
// C[M,N] = A[M,K] * B[N,K]^T.  CTA tile 128x256, K-chunk 64, 2-stage cp.async.
// Rows padded to 68 floats (272B): ldmatrix 8-lane phases conflict-free.
#define ROWF    68
#define ROWB    272u
#define A_FLT   (128*ROWF)            // 8704 floats
#define ST_FLT  (A_FLT + 256*ROWF)    // 26112 floats
#define ST_BYTE (ST_FLT*4)            // 104448 bytes
#define GSMEM   (2*ST_BYTE)           // 208896

template<int EPI>
__global__ void __launch_bounds__(256, 1) gemm_mma(
    const float* __restrict__ A, const float* __restrict__ B,
    const float* __restrict__ bias, const float* __restrict__ res,
    float* __restrict__ C, int M, int N, int K)
{
    extern __shared__ float sm[];
    const uint32_t smb = smem_u32(sm);
    const int tid  = threadIdx.x;
    const int wid  = tid >> 5;
    const int lane = tid & 31;
    const int g = lane >> 2, c = lane & 3;
    const int wy = wid & 1, wx = wid >> 1;
    const int m0 = blockIdx.y * 128;
    const int n0 = blockIdx.x * 256;
    const int nch = K >> 6;

    // cp.async: per chunk, A = 8 x 16B, B = 16 x 16B per thread
    const float* asrc[8]; uint32_t adst[8];
    const float* bsrc[16]; uint32_t bdst[16];
    #pragma unroll
    for (int i = 0; i < 8; i++) {
        int idx = tid + i * 256, row = idx >> 4, j = idx & 15;
        asrc[i] = A + (size_t)(m0 + row) * K + j * 4;
        adst[i] = row * ROWB + j * 16u;
    }
    #pragma unroll
    for (int i = 0; i < 16; i++) {
        int idx = tid + i * 256, row = idx >> 4, j = idx & 15;
        bsrc[i] = B + (size_t)(n0 + row) * K + j * 4;
        bdst[i] = (uint32_t)A_FLT * 4u + row * ROWB + j * 16u;
    }

    // prologue: chunk 0 -> stage 0
    {
        uint32_t sb = smb;
        #pragma unroll
        for (int i = 0; i < 8; i++)
            asm volatile("cp.async.cg.shared.global [%0], [%1], 16;"
                         :: "r"(sb + adst[i]), "l"(asrc[i]));
        #pragma unroll
        for (int i = 0; i < 16; i++)
            asm volatile("cp.async.cg.shared.global [%0], [%1], 16;"
                         :: "r"(sb + bdst[i]), "l"(bsrc[i]));
        asm volatile("cp.async.commit_group;");
    }

    float acc[4][8][4] = {};
    // ldmatrix lane addressing: row 0..15 within 16-row tile, half = k 0-3 / 4-7
    const uint32_t lrow = (uint32_t)((lane & 7) | (((lane >> 3) & 1) << 3));
    const uint32_t lhalf = (uint32_t)(lane >> 4);

    for (int ch = 0; ch < nch; ch++) {
        asm volatile("cp.async.wait_group 0;");
        __syncthreads();

        int ch2 = ch + 1;
        if (ch2 < nch) {
            uint32_t sb = smb + (ch2 & 1) * ST_BYTE;
            #pragma unroll
            for (int i = 0; i < 8; i++)
                asm volatile("cp.async.cg.shared.global [%0], [%1], 16;"
                             :: "r"(sb + adst[i]), "l"(asrc[i] + ch2 * 64));
            #pragma unroll
            for (int i = 0; i < 16; i++)
                asm volatile("cp.async.cg.shared.global [%0], [%1], 16;"
                             :: "r"(sb + bdst[i]), "l"(bsrc[i] + ch2 * 64));
        }
        asm volatile("cp.async.commit_group;");

        const uint32_t stb = smb + (ch & 1) * ST_BYTE;
        const uint32_t abase = stb + (uint32_t)(wy * 64 + lrow) * ROWB + lhalf * 16u;
        const uint32_t bbase = stb + (uint32_t)A_FLT * 4u
                             + (uint32_t)(wx * 64 + lrow) * ROWB + lhalf * 16u;

        #pragma unroll
        for (int ks = 0; ks < 8; ks++) {
            uint32_t koff = (uint32_t)ks * 32u;
            uint32_t af[4][4], bf[8][2];
            #pragma unroll
            for (int mf = 0; mf < 4; mf++)
                ldsm_x4(af[mf], abase + (uint32_t)mf * (16u * ROWB) + koff);
            #pragma unroll
            for (int np = 0; np < 4; np++) {
                uint32_t q[4];
                ldsm_x4(q, bbase + (uint32_t)np * (16u * ROWB) + koff);
                bf[2*np][0]   = q[0]; bf[2*np][1]   = q[2];
                bf[2*np+1][0] = q[1]; bf[2*np+1][1] = q[3];
            }
            #pragma unroll
            for (int mf = 0; mf < 4; mf++)
                #pragma unroll
                for (int nf = 0; nf < 8; nf++)
                    mma_tf32(acc[mf][nf], af[mf], bf[nf]);
        }
    }

    // epilogue
    const int mbase = m0 + wy * 64;
    const int nbase = n0 + wx * 64;
    #pragma unroll
    for (int mf = 0; mf < 4; mf++) {
        int r0 = mbase + mf * 16 + g;
        #pragma unroll
        for (int nf = 0; nf < 8; nf++) {
            int col = nbase + nf * 8 + c * 2;
            float v0 = acc[mf][nf][0], v1 = acc[mf][nf][1];
            float v2 = acc[mf][nf][2], v3 = acc[mf][nf][3];
            if (EPI >= 1) {
                float b0 = bias[col], b1 = bias[col + 1];
                v0 += b0; v1 += b1; v2 += b0; v3 += b1;
            }
            if (EPI == 1) {
                float2 r01 = *(const float2*)(res + (size_t)r0 * N + col);
                float2 r23 = *(const float2*)(res + (size_t)(r0 + 8) * N + col);
                v0 += r01.x; v1 += r01.y; v2 += r23.x; v3 += r23.y;
            }
            if (EPI == 2) {
                v0 = to_tf32(v0 * normcdff(v0));
                v1 = to_tf32(v1 * normcdff(v1));
                v2 = to_tf32(v2 * normcdff(v2));
                v3 = to_tf32(v3 * normcdff(v3));
            }
            *(float2*)(C + (size_t)r0 * N + col)       = make_float2(v0, v1);
            *(float2*)(C + (size_t)(r0 + 8) * N + col) = make_float2(v2, v3);
        }
    }
}

// ---------------- Flash attention with tf32 mma.sync ----------------
#define FQ_STR 68
#define FV_STR 72
#define FSM_QS 0
#define FSM_KS (64*FQ_STR)
#define FSM_VS (FSM_KS + 64*FQ_STR)
#define FSM_PS (FSM_VS + 64*FV_STR)
#define FSM_MK (FSM_PS + 4*16*FQ_STR)
#define FSM_TOT ((FSM_MK + 64) * 4)        // 70912 bytes

__global__ void __launch_bounds__(128) flashm_k(
    const float* __restrict__ qkv, const int* __restrict__ ids,
    float* __restrict__ o)
{
    extern __shared__ float sm[];
    float* Qs = sm + FSM_QS;
    float* Ks = sm + FSM_KS;
    float* Vs = sm + FSM_VS;
    float* mk = sm + FSM_MK;

    const int tid = threadIdx.x;
    const int wid = tid >> 5, lane = tid & 31;
    const int g = lane >> 2, c = lane & 3;
    const int qt = blockIdx.x, h = blockIdx.y, b = blockIdx.z;
    const int q0 = qt * 64;
    const size_t rstr = 3 * CD;
    float* Pw = sm + FSM_PS + wid * 16 * FQ_STR;

    for (int i = tid; i < 1024; i += 128) {
        int r = i >> 4, c4 = (i & 15) << 2;
        float4 v = *(const float4*)(qkv + (size_t)(b*CN + q0 + r) * rstr + h*64 + c4);
        float* q = &Qs[r*FQ_STR + c4];
        q[0] = to_tf32(v.x * 0.125f); q[1] = to_tf32(v.y * 0.125f);
        q[2] = to_tf32(v.z * 0.125f); q[3] = to_tf32(v.w * 0.125f);
    }

    float oa[8][4] = {};
    float m0 = -1e30f, m1 = -1e30f, l0 = 0.f, l1 = 0.f;
    const float* Qw = Qs + (wid * 16) * FQ_STR;

    for (int kt = 0; kt < 16; kt++) {
        int k0 = kt * 64;
        __syncthreads();
        for (int i = tid; i < 1024; i += 128) {
            int r = i >> 4, c4 = (i & 15) << 2;
            const float* gk = qkv + (size_t)(b*CN + k0 + r) * rstr + CD + h*64 + c4;
            float4 v = *(const float4*)gk;
            float* kp = &Ks[r*FQ_STR + c4];
            kp[0] = to_tf32(v.x); kp[1] = to_tf32(v.y); kp[2] = to_tf32(v.z); kp[3] = to_tf32(v.w);
            float4 w = *(const float4*)(gk + CD);
            float* vp = &Vs[r*FV_STR + c4];
            vp[0] = to_tf32(w.x); vp[1] = to_tf32(w.y); vp[2] = to_tf32(w.z); vp[3] = to_tf32(w.w);
        }
        if (tid < 64) mk[tid] = -1.25e8f * (float)ids[b*CN + k0 + tid];
        __syncthreads();

        float sa[8][4] = {};
        #pragma unroll
        for (int ks = 0; ks < 8; ks++) {
            uint32_t a[4];
            a[0] = __float_as_uint(Qw[g*FQ_STR + ks*8 + c]);
            a[1] = __float_as_uint(Qw[(g+8)*FQ_STR + ks*8 + c]);
            a[2] = __float_as_uint(Qw[g*FQ_STR + ks*8 + c + 4]);
            a[3] = __float_as_uint(Qw[(g+8)*FQ_STR + ks*8 + c + 4]);
            #pragma unroll
            for (int nf = 0; nf < 8; nf++) {
                uint32_t bb[2];
                bb[0] = __float_as_uint(Ks[(nf*8+g)*FQ_STR + ks*8 + c]);
                bb[1] = __float_as_uint(Ks[(nf*8+g)*FQ_STR + ks*8 + c + 4]);
                mma_tf32(sa[nf], a, bb);
            }
        }

        float rmax0 = -1e30f, rmax1 = -1e30f;
        #pragma unroll
        for (int nf = 0; nf < 8; nf++) {
            float mv0 = mk[nf*8 + 2*c], mv1 = mk[nf*8 + 2*c + 1];
            sa[nf][0] += mv0; sa[nf][1] += mv1;
            sa[nf][2] += mv0; sa[nf][3] += mv1;
            rmax0 = fmaxf(rmax0, fmaxf(sa[nf][0], sa[nf][1]));
            rmax1 = fmaxf(rmax1, fmaxf(sa[nf][2], sa[nf][3]));
        }
        rmax0 = fmaxf(rmax0, __shfl_xor_sync(0xffffffffu, rmax0, 1));
        rmax0 = fmaxf(rmax0, __shfl_xor_sync(0xffffffffu, rmax0, 2));
        rmax1 = fmaxf(rmax1, __shfl_xor_sync(0xffffffffu, rmax1, 1));
        rmax1 = fmaxf(rmax1, __shfl_xor_sync(0xffffffffu, rmax1, 2));
        float mn0 = fmaxf(m0, rmax0), mn1 = fmaxf(m1, rmax1);
        float al0 = __expf(m0 - mn0), al1 = __expf(m1 - mn1);
        m0 = mn0; m1 = mn1;
        float ps0 = 0.f, ps1 = 0.f;
        #pragma unroll
        for (int nf = 0; nf < 8; nf++) {
            float p0 = __expf(sa[nf][0] - mn0);
            float p1 = __expf(sa[nf][1] - mn0);
            float p2 = __expf(sa[nf][2] - mn1);
            float p3 = __expf(sa[nf][3] - mn1);
            ps0 += p0 + p1; ps1 += p2 + p3;
            *(float2*)&Pw[g*FQ_STR + nf*8 + 2*c]     = make_float2(to_tf32(p0), to_tf32(p1));
            *(float2*)&Pw[(g+8)*FQ_STR + nf*8 + 2*c] = make_float2(to_tf32(p2), to_tf32(p3));
        }
        ps0 += __shfl_xor_sync(0xffffffffu, ps0, 1);
        ps0 += __shfl_xor_sync(0xffffffffu, ps0, 2);
        ps1 += __shfl_xor_sync(0xffffffffu, ps1, 1);
        ps1 += __shfl_xor_sync(0xffffffffu, ps1, 2);
        l0 = l0 * al0 + ps0;
        l1 = l1 * al1 + ps1;
        #pragma unroll
        for (int nf = 0; nf < 8; nf++) {
            oa[nf][0] *= al0; oa[nf][1] *= al0;
            oa[nf][2] *= al1; oa[nf][3] *= al1;
        }
        __syncwarp();

        #pragma unroll
        for (int ks = 0; ks < 8; ks++) {
            uint32_t a[4];
            a[0] = __float_as_uint(Pw[g*FQ_STR + ks*8 + c]);
            a[1] = __float_as_uint(Pw[(g+8)*FQ_STR + ks*8 + c]);
            a[2] = __float_as_uint(Pw[g*FQ_STR + ks*8 + c + 4]);
            a[3] = __float_as_uint(Pw[(g+8)*FQ_STR + ks*8 + c + 4]);
            #pragma unroll
            for (int nf = 0; nf < 8; nf++) {
                uint32_t bb[2];
                bb[0] = __float_as_uint(Vs[(ks*8 + c)*FV_STR + nf*8 + g]);
                bb[1] = __float_as_uint(Vs[(ks*8 + c + 4)*FV_STR + nf*8 + g]);
                mma_tf32(oa[nf], a, bb);
            }
        }
        __syncwarp();
    }

    float inv0 = 1.0f / l0, inv1 = 1.0f / l1;
    size_t r0 = (size_t)(b*CN + q0 + wid*16 + g) * CD + h*64;
    size_t r1 = (size_t)(b*CN + q0 + wid*16 + g + 8) * CD + h*64;
    #pragma unroll
    for (int nf = 0; nf < 8; nf++) {
        int col = nf*8 + 2*c;
        *(float2*)(o + r0 + col) = make_float2(to_tf32(oa[nf][0]*inv0), to_tf32(oa[nf][1]*inv0));
        *(float2*)(o + r1 + col) = make_float2(to_tf32(oa[nf][2]*inv1), to_tf32(oa[nf][3]*inv1));
    }
}

// ---------------- launch ----------------
extern "C" void kernel_launch(void* const* d_in, const int* in_sizes, int n_in,
                              void* d_out, int out_size)
{
    const float* x      = (const float*)d_in[0];
    const int*   ids    = (const int*)  d_in[1];
    const float* n1w    = (const float*)d_in[2];
    const float* n1b    = (const float*)d_in[3];
    const float* pin_w  = (const float*)d_in[4];
    const float* pout_w = (const float*)d_in[5];
    const float* pout_b = (const float*)d_in[6];
    const float* n2w    = (const float*)d_in[7];
    const float* n2b    = (const float*)d_in[8];
    const float* l1w    = (const float*)d_in[9];
    const float* l1b    = (const float*)d_in[10];
    const float* l2w    = (const float*)d_in[11];
    const float* l2b    = (const float*)d_in[12];
    float* out = (float*)d_out;

    float *xn, *qkv, *ao, *x1, *x2, *hh, *wq, *wo, *w1, *w2;
    cudaGetSymbolAddress((void**)&xn,  g_xn);
    cudaGetSymbolAddress((void**)&qkv, g_qkv);
    cudaGetSymbolAddress((void**)&ao,  g_ao);
    cudaGetSymbolAddress((void**)&x1,  g_x1);
    cudaGetSymbolAddress((void**)&x2,  g_x2);
    cudaGetSymbolAddress((void**)&hh,  g_h);
    cudaGetSymbolAddress((void**)&wq,  g_wq);
    cudaGetSymbolAddress((void**)&wo,  g_wo);
    cudaGetSymbolAddress((void**)&w1,  g_w1);
    cudaGetSymbolAddress((void**)&w2,  g_w2);

    cudaFuncSetAttribute(flashm_k,    cudaFuncAttributeMaxDynamicSharedMemorySize, FSM_TOT);
    cudaFuncSetAttribute(gemm_mma<0>, cudaFuncAttributeMaxDynamicSharedMemorySize, GSMEM);
    cudaFuncSetAttribute(gemm_mma<1>, cudaFuncAttributeMaxDynamicSharedMemorySize, GSMEM);
    cudaFuncSetAttribute(gemm_mma<2>, cudaFuncAttributeMaxDynamicSharedMemorySize, GSMEM);

    // 0) round weights to tf32 (RN)
    round_tf32_k<<<(3*CD*CD/4 + 255)/256, 256>>>((const float4*)pin_w,  (float4*)wq, 3*CD*CD/4);
    round_tf32_k<<<(CD*CD/4   + 255)/256, 256>>>((const float4*)pout_w, (float4*)wo, CD*CD/4);
    round_tf32_k<<<(CFF*CD/4  + 255)/256, 256>>>((const float4*)l1w,    (float4*)w1, CFF*CD/4);
    round_tf32_k<<<(CD*CFF/4  + 255)/256, 256>>>((const float4*)l2w,    (float4*)w2, CD*CFF/4);

    // 1) xn = tf32(LN1(x))
    layernorm_k<<<NTOK, 256>>>(x, n1w, n1b, xn);
    // 2) qkv = xn @ Wq^T
    gemm_mma<0><<<dim3(3*CD/256, NTOK/128), 256, GSMEM>>>(xn, wq, nullptr, nullptr, qkv, NTOK, 3*CD, CD);
    // 3) flash attention (tensor-core) -> ao
    flashm_k<<<dim3(CN/64, CH, CB), 128, FSM_TOT>>>(qkv, ids, ao);
    // 4) x1 = ao @ Wo^T + bout + xn
    gemm_mma<1><<<dim3(CD/256, NTOK/128), 256, GSMEM>>>(ao, wo, pout_b, xn, x1, NTOK, CD, CD);
    // 5) x2 = tf32(LN2(x1))
    layernorm_k<<<NTOK, 256>>>(x1, n2w, n2b, x2);
    // 6) h = tf32(gelu(x2 @ W1^T + b1))
    gemm_mma<2><<<dim3(CFF/256, NTOK/128), 256, GSMEM>>>(x2, w1, l1b, nullptr, hh, NTOK, CFF, CD);
    // 7) out = h @ W2^T + b2 + x2
    gemm_mma<1><<<dim3(CD/256, NTOK/128), 256, GSMEM>>>(hh, w2, l2b, x2, out, NTOK, CD, CFF);
}

// round 6
// speedup vs baseline: 1.0073x; 1.0073x over previous
#include <cuda_runtime.h>
#include <math.h>
#include <stdint.h>

#define CD   1024
#define CH   16
#define CFF  4096
#define CB   8
#define CN   1024
#define NTOK (CB*CN)   // 8192

// ---------------- scratch (no allocations allowed) ----------------
__device__ float g_xn [NTOK*CD];      // layernorm1(x), tf32-rounded
__device__ float g_qkv[NTOK*3*CD];    // qkv projection
__device__ float g_ao [NTOK*CD];      // attention output, tf32-rounded
__device__ float g_x1 [NTOK*CD];      // attn + residual
__device__ float g_x2 [NTOK*CD];      // layernorm2(x1), tf32-rounded
__device__ float g_h  [NTOK*CFF];     // gelu(lin1), tf32-rounded
__device__ float g_wq [3*CD*CD];      // tf32-rounded weights
__device__ float g_wo [CD*CD];
__device__ float g_w1 [CFF*CD];
__device__ float g_w2 [CD*CFF];

// ---------------- helpers ----------------
__device__ __forceinline__ uint32_t smem_u32(const void* p) {
    uint32_t a;
    asm("{ .reg .u64 t; cvta.to.shared.u64 t, %1; cvt.u32.u64 %0, t; }" : "=r"(a) : "l"(p));
    return a;
}
__device__ __forceinline__ float to_tf32(float x) {
    uint32_t u;
    asm("cvt.rna.tf32.f32 %0, %1;" : "=r"(u) : "f"(x));
    return __uint_as_float(u);
}
__device__ __forceinline__ void mma_tf32(float* d, const uint32_t* a, const uint32_t* b) {
    asm volatile(
        "mma.sync.aligned.m16n8k8.row.col.f32.tf32.tf32.f32 "
        "{%0,%1,%2,%3},{%4,%5,%6,%7},{%8,%9},{%0,%1,%2,%3};"
        : "+f"(d[0]), "+f"(d[1]), "+f"(d[2]), "+f"(d[3])
        : "r"(a[0]), "r"(a[1]), "r"(a[2]), "r"(a[3]), "r"(b[0]), "r"(b[1]));
}
__device__ __forceinline__ void ldsm_x4(uint32_t* r, uint32_t addr) {
    asm volatile("ldmatrix.sync.aligned.m8n8.x4.shared.b16 {%0,%1,%2,%3}, [%4];"
        : "=r"(r[0]), "=r"(r[1]), "=r"(r[2]), "=r"(r[3]) : "r"(addr));
}

// ---------------- tf32 RN rounding copy (weights) ----------------
__global__ void round_tf32_k(const float4* __restrict__ src, float4* __restrict__ dst, int n4) {
    int i = blockIdx.x * blockDim.x + threadIdx.x;
    if (i < n4) {
        float4 v = src[i];
        v.x = to_tf32(v.x); v.y = to_tf32(v.y); v.z = to_tf32(v.z); v.w = to_tf32(v.w);
        dst[i] = v;
    }
}

// ---------------- LayerNorm (output rounded to tf32) ----------------
__global__ void __launch_bounds__(256) layernorm_k(
    const float* __restrict__ x, const float* __restrict__ w,
    const float* __restrict__ b, float* __restrict__ y)
{
    int row = blockIdx.x;
    int tid = threadIdx.x;
    const float4* xr = (const float4*)(x + (size_t)row * CD);
    float4 xv = xr[tid];
    float s  = xv.x + xv.y + xv.z + xv.w;
    float ss = xv.x*xv.x + xv.y*xv.y + xv.z*xv.z + xv.w*xv.w;
    #pragma unroll
    for (int o = 16; o; o >>= 1) {
        s  += __shfl_xor_sync(0xffffffffu, s,  o);
        ss += __shfl_xor_sync(0xffffffffu, ss, o);
    }
    __shared__ float sm1[8], sm2[8];
    if ((tid & 31) == 0) { sm1[tid >> 5] = s; sm2[tid >> 5] = ss; }
    __syncthreads();
    float ts = 0.f, tss = 0.f;
    #pragma unroll
    for (int i = 0; i < 8; i++) { ts += sm1[i]; tss += sm2[i]; }
    float mu   = ts * (1.0f / CD);
    float var  = tss * (1.0f / CD) - mu * mu;
    float rstd = rsqrtf(var + 1e-5f);
    float4 wv = ((const float4*)w)[tid];
    float4 bv = ((const float4*)b)[tid];
    float4 ov;
    ov.x = to_tf32((xv.x - mu) * rstd * wv.x + bv.x);
    ov.y = to_tf32((xv.y - mu) * rstd * wv.y + bv.y);
    ov.z = to_tf32((xv.z - mu) * rstd * wv.z + bv.z);
    ov.w = to_tf32((xv.w - mu) * rstd * wv.w + bv.w);
    ((float4*)(y + (size_t)row * CD))[tid] = ov;
}

// ---------------- tf32 mma.sync NT GEMM (R4 pipeline + ldmatrix) ----------------
// C[M,N] = A[M,K] * B[N,K]^T.  CTA tile 128x256, K-chunk 32, 4-stage cp.async.
// Rows padded to 36 floats (144B): ldmatrix phases conflict-free (banks 4r..4r+3).
#define NST     4
#define ROWF    36
#define ROWB    144u
#define A_FLT   (128*ROWF)
#define ST_FLT  (A_FLT + 256*ROWF)
#define ST_BYTE (ST_FLT*4)            // 55296 bytes
#define GSMEM   (NST*ST_BYTE)         // 221184

template<int EPI>
__global__ void __launch_bounds__(256, 1) gemm_mma(
    const float* __restrict__ A, const float* __restrict__ B,
    const float* __restrict__ bias, const float* __restrict__ res,
    float* __restrict__ C, int M, int N, int K)
{
    extern __shared__ float sm[];
    const uint32_t smb = smem_u32(sm);
    const int tid  = threadIdx.x;
    const int wid  = tid >> 5;
    const int lane = tid & 31;
    const int g = lane >> 2, c = lane & 3;
    const int wy = wid & 1, wx = wid >> 1;
    const int m0 = blockIdx.y * 128;
    const int n0 = blockIdx.x * 256;
    const int nch = K >> 5;

    const float* asrc[4]; uint32_t adst[4];
    const float* bsrc[8]; uint32_t bdst[8];
    #pragma unroll
    for (int i = 0; i < 4; i++) {
        int idx = tid + i * 256, row = idx >> 3, j = idx & 7;
        asrc[i] = A + (size_t)(m0 + row) * K + j * 4;
        adst[i] = row * ROWB + j * 16u;
    }
    #pragma unroll
    for (int i = 0; i < 8; i++) {
        int idx = tid + i * 256, row = idx >> 3, j = idx & 7;
        bsrc[i] = B + (size_t)(n0 + row) * K + j * 4;
        bdst[i] = (uint32_t)A_FLT * 4u + row * ROWB + j * 16u;
    }

    #pragma unroll
    for (int p = 0; p < NST - 1; p++) {
        uint32_t sb = smb + p * ST_BYTE;
        #pragma unroll
        for (int i = 0; i < 4; i++)
            asm volatile("cp.async.cg.shared.global [%0], [%1], 16;"
                         :: "r"(sb + adst[i]), "l"(asrc[i] + p * 32));
        #pragma unroll
        for (int i = 0; i < 8; i++)
            asm volatile("cp.async.cg.shared.global [%0], [%1], 16;"
                         :: "r"(sb + bdst[i]), "l"(bsrc[i] + p * 32));
        asm volatile("cp.async.commit_group;");
    }

    float acc[4][8][4] = {};
    // ldmatrix lane addressing: row within 16-row tile, 16B half for k 0-3 / 4-7
    const uint32_t lrow  = (uint32_t)((lane & 7) | (((lane >> 3) & 1) << 3));
    const uint32_t lhalf = (uint32_t)(lane >> 4);

    for (int ch = 0; ch < nch; ch++) {
        asm volatile("cp.async.wait_group %0;" :: "n"(NST - 2));
        __syncthreads();

        int ch2 = ch + NST - 1;
        if (ch2 < nch) {
            uint32_t sb = smb + (ch2 % NST) * ST_BYTE;
            #pragma unroll
            for (int i = 0; i < 4; i++)
                asm volatile("cp.async.cg.shared.global [%0], [%1], 16;"
                             :: "r"(sb + adst[i]), "l"(asrc[i] + ch2 * 32));
            #pragma unroll
            for (int i = 0; i < 8; i++)
                asm volatile("cp.async.cg.shared.global [%0], [%1], 16;"
                             :: "r"(sb + bdst[i]), "l"(bsrc[i] + ch2 * 32));
        }
        asm volatile("cp.async.commit_group;");

        const uint32_t stb   = smb + (ch % NST) * ST_BYTE;
        const uint32_t abase = stb + (uint32_t)(wy * 64 + lrow) * ROWB + lhalf * 16u;
        const uint32_t bbase = stb + (uint32_t)A_FLT * 4u
                             + (uint32_t)(wx * 64 + lrow) * ROWB + lhalf * 16u;

        #pragma unroll
        for (int ks = 0; ks < 4; ks++) {
            uint32_t koff = (uint32_t)ks * 32u;
            uint32_t af[4][4], bf[8][2];
            #pragma unroll
            for (int mf = 0; mf < 4; mf++)
                ldsm_x4(af[mf], abase + (uint32_t)mf * (16u * ROWB) + koff);
            #pragma unroll
            for (int np = 0; np < 4; np++) {
                uint32_t q[4];
                ldsm_x4(q, bbase + (uint32_t)np * (16u * ROWB) + koff);
                bf[2*np][0]   = q[0]; bf[2*np][1]   = q[2];
                bf[2*np+1][0] = q[1]; bf[2*np+1][1] = q[3];
            }
            #pragma unroll
            for (int mf = 0; mf < 4; mf++)
                #pragma unroll
                for (int nf = 0; nf < 8; nf++)
                    mma_tf32(acc[mf][nf], af[mf], bf[nf]);
        }
    }

    const int mbase = m0 + wy * 64;
    const int nbase = n0 + wx * 64;
    #pragma unroll
    for (int mf = 0; mf < 4; mf++) {
        int r0 = mbase + mf * 16 + g;
        #pragma unroll
        for (int nf = 0; nf < 8; nf++) {
            int col = nbase + nf * 8 + c * 2;
            float v0 = acc[mf][nf][0], v1 = acc[mf][nf][1];
            float v2 = acc[mf][nf][2], v3 = acc[mf][nf][3];
            if (EPI >= 1) {
                float b0 = bias[col], b1 = bias[col + 1];
                v0 += b0; v1 += b1; v2 += b0; v3 += b1;
            }
            if (EPI == 1) {
                float2 r01 = *(const float2*)(res + (size_t)r0 * N + col);
                float2 r23 = *(const float2*)(res + (size_t)(r0 + 8) * N + col);
                v0 += r01.x; v1 += r01.y; v2 += r23.x; v3 += r23.y;
            }
            if (EPI == 2) {
                v0 = to_tf32(v0 * normcdff(v0));
                v1 = to_tf32(v1 * normcdff(v1));
                v2 = to_tf32(v2 * normcdff(v2));
                v3 = to_tf32(v3 * normcdff(v3));
            }
            *(float2*)(C + (size_t)r0 * N + col)       = make_float2(v0, v1);
            *(float2*)(C + (size_t)(r0 + 8) * N + col) = make_float2(v2, v3);
        }
    }
}

// ---------------- Flash attention with tf32 mma.sync ----------------
#define FQ_STR 68
#define FV_STR 72
#define FSM_QS 0
#define FSM_KS (64*FQ_STR)
#define FSM_VS (FSM_KS + 64*FQ_STR)
#define FSM_PS (FSM_VS + 64*FV_STR)
#define FSM_MK (FSM_PS + 4*16*FQ_STR)
#define FSM_TOT ((FSM_MK + 64) * 4)        // 70912 bytes

__global__ void __launch_bounds__(128) flashm_k(
    const float* __restrict__ qkv, const int* __restrict__ ids,
    float* __restrict__ o)
{
    extern __shared__ float sm[];
    float* Qs = sm + FSM_QS;
    float* Ks = sm + FSM_KS;
    float* Vs = sm + FSM_VS;
    float* mk = sm + FSM_MK;

    const int tid = threadIdx.x;
    const int wid = tid >> 5, lane = tid & 31;
    const int g = lane >> 2, c = lane & 3;
    const int qt = blockIdx.x, h = blockIdx.y, b = blockIdx.z;
    const int q0 = qt * 64;
    const size_t rstr = 3 * CD;
    float* Pw = sm + FSM_PS + wid * 16 * FQ_STR;

    for (int i = tid; i < 1024; i += 128) {
        int r = i >> 4, c4 = (i & 15) << 2;
        float4 v = *(const float4*)(qkv + (size_t)(b*CN + q0 + r) * rstr + h*64 + c4);
        float* q = &Qs[r*FQ_STR + c4];
        q[0] = to_tf32(v.x * 0.125f); q[1] = to_tf32(v.y * 0.125f);
        q[2] = to_tf32(v.z * 0.125f); q[3] = to_tf32(v.w * 0.125f);
    }

    float oa[8][4] = {};
    float m0 = -1e30f, m1 = -1e30f, l0 = 0.f, l1 = 0.f;
    const float* Qw = Qs + (wid * 16) * FQ_STR;

    for (int kt = 0; kt < 16; kt++) {
        int k0 = kt * 64;
        __syncthreads();
        for (int i = tid; i < 1024; i += 128) {
            int r = i >> 4, c4 = (i & 15) << 2;
            const float* gk = qkv + (size_t)(b*CN + k0 + r) * rstr + CD + h*64 + c4;
            float4 v = *(const float4*)gk;
            float* kp = &Ks[r*FQ_STR + c4];
            kp[0] = to_tf32(v.x); kp[1] = to_tf32(v.y); kp[2] = to_tf32(v.z); kp[3] = to_tf32(v.w);
            float4 w = *(const float4*)(gk + CD);
            float* vp = &Vs[r*FV_STR + c4];
            vp[0] = to_tf32(w.x); vp[1] = to_tf32(w.y); vp[2] = to_tf32(w.z); vp[3] = to_tf32(w.w);
        }
        if (tid < 64) mk[tid] = -1.25e8f * (float)ids[b*CN + k0 + tid];
        __syncthreads();

        float sa[8][4] = {};
        #pragma unroll
        for (int ks = 0; ks < 8; ks++) {
            uint32_t a[4];
            a[0] = __float_as_uint(Qw[g*FQ_STR + ks*8 + c]);
            a[1] = __float_as_uint(Qw[(g+8)*FQ_STR + ks*8 + c]);
            a[2] = __float_as_uint(Qw[g*FQ_STR + ks*8 + c + 4]);
            a[3] = __float_as_uint(Qw[(g+8)*FQ_STR + ks*8 + c + 4]);
            #pragma unroll
            for (int nf = 0; nf < 8; nf++) {
                uint32_t bb[2];
                bb[0] = __float_as_uint(Ks[(nf*8+g)*FQ_STR + ks*8 + c]);
                bb[1] = __float_as_uint(Ks[(nf*8+g)*FQ_STR + ks*8 + c + 4]);
                mma_tf32(sa[nf], a, bb);
            }
        }

        float rmax0 = -1e30f, rmax1 = -1e30f;
        #pragma unroll
        for (int nf = 0; nf < 8; nf++) {
            float mv0 = mk[nf*8 + 2*c], mv1 = mk[nf*8 + 2*c + 1];
            sa[nf][0] += mv0; sa[nf][1] += mv1;
            sa[nf][2] += mv0; sa[nf][3] += mv1;
            rmax0 = fmaxf(rmax0, fmaxf(sa[nf][0], sa[nf][1]));
            rmax1 = fmaxf(rmax1, fmaxf(sa[nf][2], sa[nf][3]));
        }
        rmax0 = fmaxf(rmax0, __shfl_xor_sync(0xffffffffu, rmax0, 1));
        rmax0 = fmaxf(rmax0, __shfl_xor_sync(0xffffffffu, rmax0, 2));
        rmax1 = fmaxf(rmax1, __shfl_xor_sync(0xffffffffu, rmax1, 1));
        rmax1 = fmaxf(rmax1, __shfl_xor_sync(0xffffffffu, rmax1, 2));
        float mn0 = fmaxf(m0, rmax0), mn1 = fmaxf(m1, rmax1);
        float al0 = __expf(m0 - mn0), al1 = __expf(m1 - mn1);
        m0 = mn0; m1 = mn1;
        float ps0 = 0.f, ps1 = 0.f;
        #pragma unroll
        for (int nf = 0; nf < 8; nf++) {
            float p0 = __expf(sa[nf][0] - mn0);
            float p1 = __expf(sa[nf][1] - mn0);
            float p2 = __expf(sa[nf][2] - mn1);
            float p3 = __expf(sa[nf][3] - mn1);
            ps0 += p0 + p1; ps1 += p2 + p3;
            *(float2*)&Pw[g*FQ_STR + nf*8 + 2*c]     = make_float2(to_tf32(p0), to_tf32(p1));
            *(float2*)&Pw[(g+8)*FQ_STR + nf*8 + 2*c] = make_float2(to_tf32(p2), to_tf32(p3));
        }
        ps0 += __shfl_xor_sync(0xffffffffu, ps0, 1);
        ps0 += __shfl_xor_sync(0xffffffffu, ps0, 2);
        ps1 += __shfl_xor_sync(0xffffffffu, ps1, 1);
        ps1 += __shfl_xor_sync(0xffffffffu, ps1, 2);
        l0 = l0 * al0 + ps0;
        l1 = l1 * al1 + ps1;
        #pragma unroll
        for (int nf = 0; nf < 8; nf++) {
            oa[nf][0] *= al0; oa[nf][1] *= al0;
            oa[nf][2] *= al1; oa[nf][3] *= al1;
        }
        __syncwarp();

        #pragma unroll
        for (int ks = 0; ks < 8; ks++) {
            uint32_t a[4];
            a[0] = __float_as_uint(Pw[g*FQ_STR + ks*8 + c]);
            a[1] = __float_as_uint(Pw[(g+8)*FQ_STR + ks*8 + c]);
            a[2] = __float_as_uint(Pw[g*FQ_STR + ks*8 + c + 4]);
            a[3] = __float_as_uint(Pw[(g+8)*FQ_STR + ks*8 + c + 4]);
            #pragma unroll
            for (int nf = 0; nf < 8; nf++) {
                uint32_t bb[2];
                bb[0] = __float_as_uint(Vs[(ks*8 + c)*FV_STR + nf*8 + g]);
                bb[1] = __float_as_uint(Vs[(ks*8 + c + 4)*FV_STR + nf*8 + g]);
                mma_tf32(oa[nf], a, bb);
            }
        }
        __syncwarp();
    }

    float inv0 = 1.0f / l0, inv1 = 1.0f / l1;
    size_t r0 = (size_t)(b*CN + q0 + wid*16 + g) * CD + h*64;
    size_t r1 = (size_t)(b*CN + q0 + wid*16 + g + 8) * CD + h*64;
    #pragma unroll
    for (int nf = 0; nf < 8; nf++) {
        int col = nf*8 + 2*c;
        *(float2*)(o + r0 + col) = make_float2(to_tf32(oa[nf][0]*inv0), to_tf32(oa[nf][1]*inv0));
        *(float2*)(o + r1 + col) = make_float2(to_tf32(oa[nf][2]*inv1), to_tf32(oa[nf][3]*inv1));
    }
}

// ---------------- launch ----------------
extern "C" void kernel_launch(void* const* d_in, const int* in_sizes, int n_in,
                              void* d_out, int out_size)
{
    const float* x      = (const float*)d_in[0];
    const int*   ids    = (const int*)  d_in[1];
    const float* n1w    = (const float*)d_in[2];
    const float* n1b    = (const float*)d_in[3];
    const float* pin_w  = (const float*)d_in[4];
    const float* pout_w = (const float*)d_in[5];
    const float* pout_b = (const float*)d_in[6];
    const float* n2w    = (const float*)d_in[7];
    const float* n2b    = (const float*)d_in[8];
    const float* l1w    = (const float*)d_in[9];
    const float* l1b    = (const float*)d_in[10];
    const float* l2w    = (const float*)d_in[11];
    const float* l2b    = (const float*)d_in[12];
    float* out = (float*)d_out;

    float *xn, *qkv, *ao, *x1, *x2, *hh, *wq, *wo, *w1, *w2;
    cudaGetSymbolAddress((void**)&xn,  g_xn);
    cudaGetSymbolAddress((void**)&qkv, g_qkv);
    cudaGetSymbolAddress((void**)&ao,  g_ao);
    cudaGetSymbolAddress((void**)&x1,  g_x1);
    cudaGetSymbolAddress((void**)&x2,  g_x2);
    cudaGetSymbolAddress((void**)&hh,  g_h);
    cudaGetSymbolAddress((void**)&wq,  g_wq);
    cudaGetSymbolAddress((void**)&wo,  g_wo);
    cudaGetSymbolAddress((void**)&w1,  g_w1);
    cudaGetSymbolAddress((void**)&w2,  g_w2);

    cudaFuncSetAttribute(flashm_k,    cudaFuncAttributeMaxDynamicSharedMemorySize, FSM_TOT);
    cudaFuncSetAttribute(gemm_mma<0>, cudaFuncAttributeMaxDynamicSharedMemorySize, GSMEM);
    cudaFuncSetAttribute(gemm_mma<1>, cudaFuncAttributeMaxDynamicSharedMemorySize, GSMEM);
    cudaFuncSetAttribute(gemm_mma<2>, cudaFuncAttributeMaxDynamicSharedMemorySize, GSMEM);

    // 0) round weights to tf32 (RN)
    round_tf32_k<<<(3*CD*CD/4 + 255)/256, 256>>>((const float4*)pin_w,  (float4*)wq, 3*CD*CD/4);
    round_tf32_k<<<(CD*CD/4   + 255)/256, 256>>>((const float4*)pout_w, (float4*)wo, CD*CD/4);
    round_tf32_k<<<(CFF*CD/4  + 255)/256, 256>>>((const float4*)l1w,    (float4*)w1, CFF*CD/4);
    round_tf32_k<<<(CD*CFF/4  + 255)/256, 256>>>((const float4*)l2w,    (float4*)w2, CD*CFF/4);

    // 1) xn = tf32(LN1(x))
    layernorm_k<<<NTOK, 256>>>(x, n1w, n1b, xn);
    // 2) qkv = xn @ Wq^T
    gemm_mma<0><<<dim3(3*CD/256, NTOK/128), 256, GSMEM>>>(xn, wq, nullptr, nullptr, qkv, NTOK, 3*CD, CD);
    // 3) flash attention (tensor-core) -> ao
    flashm_k<<<dim3(CN/64, CH, CB), 128, FSM_TOT>>>(qkv, ids, ao);
    // 4) x1 = ao @ Wo^T + bout + xn
    gemm_mma<1><<<dim3(CD/256, NTOK/128), 256, GSMEM>>>(ao, wo, pout_b, xn, x1, NTOK, CD, CD);
    // 5) x2 = tf32(LN2(x1))
    layernorm_k<<<NTOK, 256>>>(x1, n2w, n2b, x2);
    // 6) h = tf32(gelu(x2 @ W1^T + b1))
    gemm_mma<2><<<dim3(CFF/256, NTOK/128), 256, GSMEM>>>(x2, w1, l1b, nullptr, hh, NTOK, CFF, CD);
    // 7) out = h @ W2^T + b2 + x2
    gemm_mma<1><<<dim3(CD/256, NTOK/128), 256, GSMEM>>>(hh, w2, l2b, x2, out, NTOK, CD, CFF);
}

// round 7
// speedup vs baseline: 1.7120x; 1.6996x over previous
#include <cuda_runtime.h>
#include <cuda_fp16.h>
#include <math.h>
#include <stdint.h>

#define CD   1024
#define CH   16
#define CFF  4096
#define CB   8
#define CN   1024
#define NTOK (CB*CN)   // 8192

// ---------------- scratch (no allocations allowed) ----------------
__device__ __half g_xn_h [NTOK*CD];     // LN1 out, fp16 (GEMM operand)
__device__ float  g_xn_f [NTOK*CD];     // LN1 out, fp32 (residual)
__device__ __half g_qkv_h[NTOK*3*CD];   // qkv, fp16
__device__ __half g_ao_h [NTOK*CD];     // attention out, fp16
__device__ float  g_x1_f [NTOK*CD];     // attn + residual, fp32
__device__ __half g_x2_h [NTOK*CD];     // LN2 out, fp16
__device__ float  g_x2_f [NTOK*CD];     // LN2 out, fp32 (residual)
__device__ __half g_h_h  [NTOK*CFF];    // gelu(lin1), fp16
__device__ __half g_wq_h [3*CD*CD];     // fp16 weights
__device__ __half g_wo_h [CD*CD];
__device__ __half g_w1_h [CFF*CD];
__device__ __half g_w2_h [CD*CFF];

// ---------------- helpers ----------------
__device__ __forceinline__ uint32_t smem_u32(const void* p) {
    uint32_t a;
    asm("{ .reg .u64 t; cvta.to.shared.u64 t, %1; cvt.u32.u64 %0, t; }" : "=r"(a) : "l"(p));
    return a;
}
__device__ __forceinline__ void mma_f16(float* d, const uint32_t* a, const uint32_t* b) {
    asm volatile(
        "mma.sync.aligned.m16n8k16.row.col.f32.f16.f16.f32 "
        "{%0,%1,%2,%3},{%4,%5,%6,%7},{%8,%9},{%0,%1,%2,%3};"
        : "+f"(d[0]), "+f"(d[1]), "+f"(d[2]), "+f"(d[3])
        : "r"(a[0]), "r"(a[1]), "r"(a[2]), "r"(a[3]), "r"(b[0]), "r"(b[1]));
}
__device__ __forceinline__ void ldsm_x4(uint32_t* r, uint32_t addr) {
    asm volatile("ldmatrix.sync.aligned.m8n8.x4.shared.b16 {%0,%1,%2,%3}, [%4];"
        : "=r"(r[0]), "=r"(r[1]), "=r"(r[2]), "=r"(r[3]) : "r"(addr));
}
__device__ __forceinline__ uint32_t h2u(__half2 h) { return *(uint32_t*)&h; }

// ---------------- fp16 rounding copy (weights) ----------------
__global__ void round_f16_k(const float4* __restrict__ src, uint2* __restrict__ dst, int n4) {
    int i = blockIdx.x * blockDim.x + threadIdx.x;
    if (i < n4) {
        float4 v = src[i];
        uint2 o;
        o.x = h2u(__floats2half2_rn(v.x, v.y));
        o.y = h2u(__floats2half2_rn(v.z, v.w));
        dst[i] = o;
    }
}

// ---------------- LayerNorm: fp16 + fp32 outputs ----------------
__global__ void __launch_bounds__(256) layernorm_k(
    const float* __restrict__ x, const float* __restrict__ w,
    const float* __restrict__ b, __half* __restrict__ yh, float* __restrict__ yf)
{
    int row = blockIdx.x;
    int tid = threadIdx.x;
    const float4* xr = (const float4*)(x + (size_t)row * CD);
    float4 xv = xr[tid];
    float s  = xv.x + xv.y + xv.z + xv.w;
    float ss = xv.x*xv.x + xv.y*xv.y + xv.z*xv.z + xv.w*xv.w;
    #pragma unroll
    for (int o = 16; o; o >>= 1) {
        s  += __shfl_xor_sync(0xffffffffu, s,  o);
        ss += __shfl_xor_sync(0xffffffffu, ss, o);
    }
    __shared__ float sm1[8], sm2[8];
    if ((tid & 31) == 0) { sm1[tid >> 5] = s; sm2[tid >> 5] = ss; }
    __syncthreads();
    float ts = 0.f, tss = 0.f;
    #pragma unroll
    for (int i = 0; i < 8; i++) { ts += sm1[i]; tss += sm2[i]; }
    float mu   = ts * (1.0f / CD);
    float var  = tss * (1.0f / CD) - mu * mu;
    float rstd = rsqrtf(var + 1e-5f);
    float4 wv = ((const float4*)w)[tid];
    float4 bv = ((const float4*)b)[tid];
    float4 ov;
    ov.x = (xv.x - mu) * rstd * wv.x + bv.x;
    ov.y = (xv.y - mu) * rstd * wv.y + bv.y;
    ov.z = (xv.z - mu) * rstd * wv.z + bv.z;
    ov.w = (xv.w - mu) * rstd * wv.w + bv.w;
    ((float4*)(yf + (size_t)row * CD))[tid] = ov;
    uint2 oh;
    oh.x = h2u(__floats2half2_rn(ov.x, ov.y));
    oh.y = h2u(__floats2half2_rn(ov.z, ov.w));
    ((uint2*)(yh + (size_t)row * CD))[tid] = oh;
}

// ---------------- fp16 mma.sync NT GEMM ----------------
// C[M,N] = A[M,K] * B[N,K]^T.  CTA tile 128x256, K-chunk 64 (fp16), 4-stage cp.async.
// Rows: 64 halves = 128B, padded to 144B. ldmatrix phases conflict-free.
// EPI 0: fp16 out, no bias  EPI 1: fp32 out, +bias+res  EPI 2: fp16 out, gelu(+bias)
#define NST     4
#define ROWB    144u
#define A_HALF  (128*72)              // halves in A region (128 rows x 72)
#define ST_BYTE ((128+256)*144)       // 55296 bytes
#define GSMEM   (NST*ST_BYTE)         // 221184

template<int EPI>
__global__ void __launch_bounds__(256, 1) gemm_mma(
    const __half* __restrict__ A, const __half* __restrict__ B,
    const float* __restrict__ bias, const float* __restrict__ res,
    void* __restrict__ Cv, int M, int N, int K)
{
    extern __shared__ char smc[];
    const uint32_t smb = smem_u32(smc);
    const int tid  = threadIdx.x;
    const int wid  = tid >> 5;
    const int lane = tid & 31;
    const int g = lane >> 2, c = lane & 3;
    const int wy = wid & 1, wx = wid >> 1;
    const int m0 = blockIdx.y * 128;
    const int n0 = blockIdx.x * 256;
    const int nch = K >> 6;

    // cp.async: per chunk (64 halves = 128B per row): A 4 x 16B, B 8 x 16B per thread
    const __half* asrc[4]; uint32_t adst[4];
    const __half* bsrc[8]; uint32_t bdst[8];
    #pragma unroll
    for (int i = 0; i < 4; i++) {
        int idx = tid + i * 256, row = idx >> 3, j = idx & 7;
        asrc[i] = A + (size_t)(m0 + row) * K + j * 8;
        adst[i] = row * ROWB + j * 16u;
    }
    #pragma unroll
    for (int i = 0; i < 8; i++) {
        int idx = tid + i * 256, row = idx >> 3, j = idx & 7;
        bsrc[i] = B + (size_t)(n0 + row) * K + j * 8;
        bdst[i] = (uint32_t)(A_HALF * 2) + row * ROWB + j * 16u;
    }

    #pragma unroll
    for (int p = 0; p < NST - 1; p++) {
        uint32_t sb = smb + p * ST_BYTE;
        #pragma unroll
        for (int i = 0; i < 4; i++)
            asm volatile("cp.async.cg.shared.global [%0], [%1], 16;"
                         :: "r"(sb + adst[i]), "l"(asrc[i] + p * 64));
        #pragma unroll
        for (int i = 0; i < 8; i++)
            asm volatile("cp.async.cg.shared.global [%0], [%1], 16;"
                         :: "r"(sb + bdst[i]), "l"(bsrc[i] + p * 64));
        asm volatile("cp.async.commit_group;");
    }

    float acc[4][8][4] = {};
    const uint32_t lrow  = (uint32_t)(lane & 15);
    const uint32_t lhalf = (uint32_t)(lane >> 4);

    for (int ch = 0; ch < nch; ch++) {
        asm volatile("cp.async.wait_group %0;" :: "n"(NST - 2));
        __syncthreads();

        int ch2 = ch + NST - 1;
        if (ch2 < nch) {
            uint32_t sb = smb + (ch2 & 3) * ST_BYTE;
            #pragma unroll
            for (int i = 0; i < 4; i++)
                asm volatile("cp.async.cg.shared.global [%0], [%1], 16;"
                             :: "r"(sb + adst[i]), "l"(asrc[i] + ch2 * 64));
            #pragma unroll
            for (int i = 0; i < 8; i++)
                asm volatile("cp.async.cg.shared.global [%0], [%1], 16;"
                             :: "r"(sb + bdst[i]), "l"(bsrc[i] + ch2 * 64));
        }
        asm volatile("cp.async.commit_group;");

        const uint32_t stb   = smb + (ch & 3) * ST_BYTE;
        const uint32_t abase = stb + (uint32_t)(wy * 64 + lrow) * ROWB + lhalf * 16u;
        const uint32_t bbase = stb + (uint32_t)(A_HALF * 2)
                             + (uint32_t)(wx * 64 + lrow) * ROWB + lhalf * 16u;

        #pragma unroll
        for (int ks = 0; ks < 4; ks++) {       // 4 k16-steps = K-chunk 64
            uint32_t koff = (uint32_t)ks * 32u;
            uint32_t af[4][4], bf[8][2];
            #pragma unroll
            for (int mf = 0; mf < 4; mf++)
                ldsm_x4(af[mf], abase + (uint32_t)mf * (16u * ROWB) + koff);
            #pragma unroll
            for (int np = 0; np < 4; np++) {
                uint32_t q[4];
                ldsm_x4(q, bbase + (uint32_t)np * (16u * ROWB) + koff);
                bf[2*np][0]   = q[0]; bf[2*np][1]   = q[2];
                bf[2*np+1][0] = q[1]; bf[2*np+1][1] = q[3];
            }
            #pragma unroll
            for (int mf = 0; mf < 4; mf++)
                #pragma unroll
                for (int nf = 0; nf < 8; nf++)
                    mma_f16(acc[mf][nf], af[mf], bf[nf]);
        }
    }

    const int mbase = m0 + wy * 64;
    const int nbase = n0 + wx * 64;
    #pragma unroll
    for (int mf = 0; mf < 4; mf++) {
        int r0 = mbase + mf * 16 + g;
        #pragma unroll
        for (int nf = 0; nf < 8; nf++) {
            int col = nbase + nf * 8 + c * 2;
            float v0 = acc[mf][nf][0], v1 = acc[mf][nf][1];
            float v2 = acc[mf][nf][2], v3 = acc[mf][nf][3];
            if (EPI >= 1) {
                float b0 = bias[col], b1 = bias[col + 1];
                v0 += b0; v1 += b1; v2 += b0; v3 += b1;
            }
            if (EPI == 1) {
                float* C = (float*)Cv;
                float2 r01 = *(const float2*)(res + (size_t)r0 * N + col);
                float2 r23 = *(const float2*)(res + (size_t)(r0 + 8) * N + col);
                *(float2*)(C + (size_t)r0 * N + col)       = make_float2(v0 + r01.x, v1 + r01.y);
                *(float2*)(C + (size_t)(r0 + 8) * N + col) = make_float2(v2 + r23.x, v3 + r23.y);
            } else {
                if (EPI == 2) {
                    v0 = v0 * normcdff(v0);
                    v1 = v1 * normcdff(v1);
                    v2 = v2 * normcdff(v2);
                    v3 = v3 * normcdff(v3);
                }
                __half* C = (__half*)Cv;
                *(uint32_t*)(C + (size_t)r0 * N + col)       = h2u(__floats2half2_rn(v0, v1));
                *(uint32_t*)(C + (size_t)(r0 + 8) * N + col) = h2u(__floats2half2_rn(v2, v3));
            }
        }
    }
}

// ---------------- Flash attention, fp16 mma ----------------
// Block = (b, h, 64-q-tile), 128 threads = 4 warps, warp owns 16 q rows.
// smem (halves, rows padded to 72 halves = 144B):
//   Qs[64][72] @0, Ks[64][72] @4608, Vst[64(d)][72] @9216 (V transposed),
//   Pw[4][16][72] @13824, mk(float[64]) @ byte 36864.
#define FH_STR 72
#define FH_QS  0
#define FH_KS  (64*FH_STR)
#define FH_VS  (FH_KS + 64*FH_STR)
#define FH_PW  (FH_VS + 64*FH_STR)
#define FH_END (FH_PW + 4*16*FH_STR)       // 18432 halves = 36864 B
#define FSM_TOT (FH_END*2 + 256)

__global__ void __launch_bounds__(128) flashm_k(
    const __half* __restrict__ qkv, const int* __restrict__ ids,
    __half* __restrict__ o)
{
    extern __shared__ char smc[];
    __half* smh = (__half*)smc;
    __half* Qs  = smh + FH_QS;
    __half* Ks  = smh + FH_KS;
    __half* Vst = smh + FH_VS;
    float*  mk  = (float*)(smc + FH_END*2);
    const uint32_t smb = smem_u32(smc);

    const int tid = threadIdx.x;
    const int wid = tid >> 5, lane = tid & 31;
    const int g = lane >> 2, c = lane & 3;
    const int qt = blockIdx.x, h = blockIdx.y, b = blockIdx.z;
    const int q0 = qt * 64;
    const size_t rstr = 3 * CD;

    // load Q tile (raw fp16 copy; scale applied to S later)
    for (int i = tid; i < 512; i += 128) {
        int r = i >> 3, j = i & 7;
        *(uint4*)(Qs + r * FH_STR + j * 8) =
            *(const uint4*)(qkv + (size_t)(b*CN + q0 + r) * rstr + h*64 + j*8);
    }

    float oa[8][4] = {};
    float m0 = -1e30f, m1 = -1e30f, l0 = 0.f, l1 = 0.f;

    const uint32_t lrow  = (uint32_t)(lane & 15);
    const uint32_t lhalf = (uint32_t)(lane >> 4);
    const uint32_t qbase = smb + (uint32_t)(wid*16 + lrow) * 144u + lhalf * 16u;
    const uint32_t kbase = smb + (uint32_t)(FH_KS*2) + lrow * 144u + lhalf * 16u;
    const uint32_t vbase = smb + (uint32_t)(FH_VS*2) + lrow * 144u + lhalf * 16u;
    const uint32_t pbase = smb + (uint32_t)(FH_PW*2) + (uint32_t)wid * (16u*144u)
                         + lrow * 144u + lhalf * 16u;
    __half* Pw = smh + FH_PW + wid * 16 * FH_STR;

    for (int kt = 0; kt < 16; kt++) {
        int k0 = kt * 64;
        __syncthreads();
        // K tile (copy) + V tile (transpose store)
        for (int i = tid; i < 512; i += 128) {
            int r = i >> 3, j = i & 7;
            const __half* gk = qkv + (size_t)(b*CN + k0 + r) * rstr + CD + h*64 + j*8;
            *(uint4*)(Ks + r * FH_STR + j * 8) = *(const uint4*)gk;
            uint4 vv = *(const uint4*)(gk + CD);
            const __half* vh = (const __half*)&vv;
            #pragma unroll
            for (int t = 0; t < 8; t++)
                Vst[(j*8 + t) * FH_STR + r] = vh[t];
        }
        if (tid < 64) mk[tid] = -1.25e8f * (float)ids[b*CN + k0 + tid];
        __syncthreads();

        // ---- S = Q @ K^T ----
        float sa[8][4] = {};
        #pragma unroll
        for (int ks = 0; ks < 4; ks++) {
            uint32_t koff = (uint32_t)ks * 32u;
            uint32_t a[4];
            ldsm_x4(a, qbase + koff);
            #pragma unroll
            for (int np = 0; np < 4; np++) {
                uint32_t q[4];
                ldsm_x4(q, kbase + (uint32_t)np * (16u*144u) + koff);
                uint32_t b0[2] = {q[0], q[2]}, b1[2] = {q[1], q[3]};
                mma_f16(sa[2*np],   a, b0);
                mma_f16(sa[2*np+1], a, b1);
            }
        }

        // ---- scale + mask + online softmax ----
        float rmax0 = -1e30f, rmax1 = -1e30f;
        #pragma unroll
        for (int nf = 0; nf < 8; nf++) {
            float mv0 = mk[nf*8 + 2*c], mv1 = mk[nf*8 + 2*c + 1];
            sa[nf][0] = sa[nf][0]*0.125f + mv0; sa[nf][1] = sa[nf][1]*0.125f + mv1;
            sa[nf][2] = sa[nf][2]*0.125f + mv0; sa[nf][3] = sa[nf][3]*0.125f + mv1;
            rmax0 = fmaxf(rmax0, fmaxf(sa[nf][0], sa[nf][1]));
            rmax1 = fmaxf(rmax1, fmaxf(sa[nf][2], sa[nf][3]));
        }
        rmax0 = fmaxf(rmax0, __shfl_xor_sync(0xffffffffu, rmax0, 1));
        rmax0 = fmaxf(rmax0, __shfl_xor_sync(0xffffffffu, rmax0, 2));
        rmax1 = fmaxf(rmax1, __shfl_xor_sync(0xffffffffu, rmax1, 1));
        rmax1 = fmaxf(rmax1, __shfl_xor_sync(0xffffffffu, rmax1, 2));
        float mn0 = fmaxf(m0, rmax0), mn1 = fmaxf(m1, rmax1);
        float al0 = __expf(m0 - mn0), al1 = __expf(m1 - mn1);
        m0 = mn0; m1 = mn1;
        float ps0 = 0.f, ps1 = 0.f;
        #pragma unroll
        for (int nf = 0; nf < 8; nf++) {
            float p0 = __expf(sa[nf][0] - mn0);
            float p1 = __expf(sa[nf][1] - mn0);
            float p2 = __expf(sa[nf][2] - mn1);
            float p3 = __expf(sa[nf][3] - mn1);
            ps0 += p0 + p1; ps1 += p2 + p3;
            *(uint32_t*)(Pw + g*FH_STR + nf*8 + 2*c)     = h2u(__floats2half2_rn(p0, p1));
            *(uint32_t*)(Pw + (g+8)*FH_STR + nf*8 + 2*c) = h2u(__floats2half2_rn(p2, p3));
        }
        ps0 += __shfl_xor_sync(0xffffffffu, ps0, 1);
        ps0 += __shfl_xor_sync(0xffffffffu, ps0, 2);
        ps1 += __shfl_xor_sync(0xffffffffu, ps1, 1);
        ps1 += __shfl_xor_sync(0xffffffffu, ps1, 2);
        l0 = l0 * al0 + ps0;
        l1 = l1 * al1 + ps1;
        #pragma unroll
        for (int nf = 0; nf < 8; nf++) {
            oa[nf][0] *= al0; oa[nf][1] *= al0;
            oa[nf][2] *= al1; oa[nf][3] *= al1;
        }
        __syncwarp();

        // ---- O += P @ V ----
        #pragma unroll
        for (int ks = 0; ks < 4; ks++) {
            uint32_t koff = (uint32_t)ks * 32u;
            uint32_t a[4];
            ldsm_x4(a, pbase + koff);
            #pragma unroll
            for (int np = 0; np < 4; np++) {
                uint32_t q[4];
                ldsm_x4(q, vbase + (uint32_t)np * (16u*144u) + koff);
                uint32_t b0[2] = {q[0], q[2]}, b1[2] = {q[1], q[3]};
                mma_f16(oa[2*np],   a, b0);
                mma_f16(oa[2*np+1], a, b1);
            }
        }
        __syncwarp();
    }

    // ---- epilogue ----
    float inv0 = 1.0f / l0, inv1 = 1.0f / l1;
    size_t r0 = (size_t)(b*CN + q0 + wid*16 + g) * CD + h*64;
    size_t r1 = (size_t)(b*CN + q0 + wid*16 + g + 8) * CD + h*64;
    #pragma unroll
    for (int nf = 0; nf < 8; nf++) {
        int col = nf*8 + 2*c;
        *(uint32_t*)(o + r0 + col) = h2u(__floats2half2_rn(oa[nf][0]*inv0, oa[nf][1]*inv0));
        *(uint32_t*)(o + r1 + col) = h2u(__floats2half2_rn(oa[nf][2]*inv1, oa[nf][3]*inv1));
    }
}

// ---------------- launch ----------------
extern "C" void kernel_launch(void* const* d_in, const int* in_sizes, int n_in,
                              void* d_out, int out_size)
{
    const float* x      = (const float*)d_in[0];
    const int*   ids    = (const int*)  d_in[1];
    const float* n1w    = (const float*)d_in[2];
    const float* n1b    = (const float*)d_in[3];
    const float* pin_w  = (const float*)d_in[4];
    const float* pout_w = (const float*)d_in[5];
    const float* pout_b = (const float*)d_in[6];
    const float* n2w    = (const float*)d_in[7];
    const float* n2b    = (const float*)d_in[8];
    const float* l1w    = (const float*)d_in[9];
    const float* l1b    = (const float*)d_in[10];
    const float* l2w    = (const float*)d_in[11];
    const float* l2b    = (const float*)d_in[12];
    float* out = (float*)d_out;

    __half *xnh, *qkvh, *aoh, *x2h, *hhh, *wqh, *woh, *w1h, *w2h;
    float *xnf, *x1f, *x2f;
    cudaGetSymbolAddress((void**)&xnh,  g_xn_h);
    cudaGetSymbolAddress((void**)&xnf,  g_xn_f);
    cudaGetSymbolAddress((void**)&qkvh, g_qkv_h);
    cudaGetSymbolAddress((void**)&aoh,  g_ao_h);
    cudaGetSymbolAddress((void**)&x1f,  g_x1_f);
    cudaGetSymbolAddress((void**)&x2h,  g_x2_h);
    cudaGetSymbolAddress((void**)&x2f,  g_x2_f);
    cudaGetSymbolAddress((void**)&hhh,  g_h_h);
    cudaGetSymbolAddress((void**)&wqh,  g_wq_h);
    cudaGetSymbolAddress((void**)&woh,  g_wo_h);
    cudaGetSymbolAddress((void**)&w1h,  g_w1_h);
    cudaGetSymbolAddress((void**)&w2h,  g_w2_h);

    cudaFuncSetAttribute(flashm_k,    cudaFuncAttributeMaxDynamicSharedMemorySize, FSM_TOT);
    cudaFuncSetAttribute(gemm_mma<0>, cudaFuncAttributeMaxDynamicSharedMemorySize, GSMEM);
    cudaFuncSetAttribute(gemm_mma<1>, cudaFuncAttributeMaxDynamicSharedMemorySize, GSMEM);
    cudaFuncSetAttribute(gemm_mma<2>, cudaFuncAttributeMaxDynamicSharedMemorySize, GSMEM);

    // 0) weights -> fp16
    round_f16_k<<<(3*CD*CD/4 + 255)/256, 256>>>((const float4*)pin_w,  (uint2*)wqh, 3*CD*CD/4);
    round_f16_k<<<(CD*CD/4   + 255)/256, 256>>>((const float4*)pout_w, (uint2*)woh, CD*CD/4);
    round_f16_k<<<(CFF*CD/4  + 255)/256, 256>>>((const float4*)l1w,    (uint2*)w1h, CFF*CD/4);
    round_f16_k<<<(CD*CFF/4  + 255)/256, 256>>>((const float4*)l2w,    (uint2*)w2h, CD*CFF/4);

    // 1) xn = LN1(x)  (fp16 operand + fp32 residual)
    layernorm_k<<<NTOK, 256>>>(x, n1w, n1b, xnh, xnf);
    // 2) qkv = xn @ Wq^T  (fp16 out)
    gemm_mma<0><<<dim3(3*CD/256, NTOK/128), 256, GSMEM>>>(xnh, wqh, nullptr, nullptr, qkvh, NTOK, 3*CD, CD);
    // 3) flash attention -> ao (fp16)
    flashm_k<<<dim3(CN/64, CH, CB), 128, FSM_TOT>>>(qkvh, ids, aoh);
    // 4) x1 = ao @ Wo^T + bout + xn  (fp32 out)
    gemm_mma<1><<<dim3(CD/256, NTOK/128), 256, GSMEM>>>(aoh, woh, pout_b, xnf, x1f, NTOK, CD, CD);
    // 5) x2 = LN2(x1)
    layernorm_k<<<NTOK, 256>>>(x1f, n2w, n2b, x2h, x2f);
    // 6) h = gelu(x2 @ W1^T + b1)  (fp16 out)
    gemm_mma<2><<<dim3(CFF/256, NTOK/128), 256, GSMEM>>>(x2h, w1h, l1b, nullptr, hhh, NTOK, CFF, CD);
    // 7) out = h @ W2^T + b2 + x2  (fp32 out)
    gemm_mma<1><<<dim3(CD/256, NTOK/128), 256, GSMEM>>>(hhh, w2h, l2b, x2f, out, NTOK, CD, CFF);
}

// round 8
// speedup vs baseline: 1.8934x; 1.1060x over previous
#include <cuda_runtime.h>
#include <cuda_fp16.h>
#include <math.h>
#include <stdint.h>

#define CD   1024
#define CH   16
#define CFF  4096
#define CB   8
#define CN   1024
#define NTOK (CB*CN)   // 8192

// ---------------- scratch (no allocations allowed) ----------------
__device__ __half g_xn_h [NTOK*CD];     // LN1 out, fp16 (GEMM operand)
__device__ float  g_xn_f [NTOK*CD];     // LN1 out, fp32 (residual)
__device__ __half g_qkv_h[NTOK*3*CD];   // qkv, fp16
__device__ __half g_ao_h [NTOK*CD];     // attention out, fp16
__device__ float  g_x1_f [NTOK*CD];     // attn + residual, fp32
__device__ __half g_x2_h [NTOK*CD];     // LN2 out, fp16
__device__ float  g_x2_f [NTOK*CD];     // LN2 out, fp32 (residual)
__device__ __half g_h_h  [NTOK*CFF];    // gelu(lin1), fp16
__device__ __half g_wq_h [3*CD*CD];     // fp16 weights
__device__ __half g_wo_h [CD*CD];
__device__ __half g_w1_h [CFF*CD];
__device__ __half g_w2_h [CD*CFF];

// ---------------- helpers ----------------
__device__ __forceinline__ uint32_t smem_u32(const void* p) {
    uint32_t a;
    asm("{ .reg .u64 t; cvta.to.shared.u64 t, %1; cvt.u32.u64 %0, t; }" : "=r"(a) : "l"(p));
    return a;
}
__device__ __forceinline__ void mma_f16(float* d, const uint32_t* a, const uint32_t* b) {
    asm volatile(
        "mma.sync.aligned.m16n8k16.row.col.f32.f16.f16.f32 "
        "{%0,%1,%2,%3},{%4,%5,%6,%7},{%8,%9},{%0,%1,%2,%3};"
        : "+f"(d[0]), "+f"(d[1]), "+f"(d[2]), "+f"(d[3])
        : "r"(a[0]), "r"(a[1]), "r"(a[2]), "r"(a[3]), "r"(b[0]), "r"(b[1]));
}
__device__ __forceinline__ void ldsm_x4(uint32_t* r, uint32_t addr) {
    asm volatile("ldmatrix.sync.aligned.m8n8.x4.shared.b16 {%0,%1,%2,%3}, [%4];"
        : "=r"(r[0]), "=r"(r[1]), "=r"(r[2]), "=r"(r[3]) : "r"(addr));
}
__device__ __forceinline__ uint32_t h2u(__half2 h) { return *(uint32_t*)&h; }

// ---------------- fp16 rounding copy (weights) ----------------
__global__ void round_f16_k(const float4* __restrict__ src, uint2* __restrict__ dst, int n4) {
    int i = blockIdx.x * blockDim.x + threadIdx.x;
    if (i < n4) {
        float4 v = src[i];
        uint2 o;
        o.x = h2u(__floats2half2_rn(v.x, v.y));
        o.y = h2u(__floats2half2_rn(v.z, v.w));
        dst[i] = o;
    }
}

// ---------------- LayerNorm: fp16 + fp32 outputs ----------------
__global__ void __launch_bounds__(256) layernorm_k(
    const float* __restrict__ x, const float* __restrict__ w,
    const float* __restrict__ b, __half* __restrict__ yh, float* __restrict__ yf)
{
    int row = blockIdx.x;
    int tid = threadIdx.x;
    const float4* xr = (const float4*)(x + (size_t)row * CD);
    float4 xv = xr[tid];
    float s  = xv.x + xv.y + xv.z + xv.w;
    float ss = xv.x*xv.x + xv.y*xv.y + xv.z*xv.z + xv.w*xv.w;
    #pragma unroll
    for (int o = 16; o; o >>= 1) {
        s  += __shfl_xor_sync(0xffffffffu, s,  o);
        ss += __shfl_xor_sync(0xffffffffu, ss, o);
    }
    __shared__ float sm1[8], sm2[8];
    if ((tid & 31) == 0) { sm1[tid >> 5] = s; sm2[tid >> 5] = ss; }
    __syncthreads();
    float ts = 0.f, tss = 0.f;
    #pragma unroll
    for (int i = 0; i < 8; i++) { ts += sm1[i]; tss += sm2[i]; }
    float mu   = ts * (1.0f / CD);
    float var  = tss * (1.0f / CD) - mu * mu;
    float rstd = rsqrtf(var + 1e-5f);
    float4 wv = ((const float4*)w)[tid];
    float4 bv = ((const float4*)b)[tid];
    float4 ov;
    ov.x = (xv.x - mu) * rstd * wv.x + bv.x;
    ov.y = (xv.y - mu) * rstd * wv.y + bv.y;
    ov.z = (xv.z - mu) * rstd * wv.z + bv.z;
    ov.w = (xv.w - mu) * rstd * wv.w + bv.w;
    ((float4*)(yf + (size_t)row * CD))[tid] = ov;
    uint2 oh;
    oh.x = h2u(__floats2half2_rn(ov.x, ov.y));
    oh.y = h2u(__floats2half2_rn(ov.z, ov.w));
    ((uint2*)(yh + (size_t)row * CD))[tid] = oh;
}

// ---------------- fp16 mma.sync NT GEMM, 2 CTAs/SM ----------------
// C[M,N] = A[M,K] * B[N,K]^T.  CTA tile 128x128, 8 warps (warp 32x64),
// K-chunk 64, 3-stage cp.async, 2 CTAs/SM hide sync/fill bubbles.
// Rows: 64 halves = 128B, padded to 144B; ldmatrix conflict-free.
#define NST     3
#define ROWB    144u
#define ATILE_B 18432u                 // 128 rows x 144B
#define ST_BYTE (2u*ATILE_B)           // 36864 (A + B)
#define GSMEM   (NST*ST_BYTE)          // 110592

template<int EPI>
__global__ void __launch_bounds__(256, 2) gemm_mma(
    const __half* __restrict__ A, const __half* __restrict__ B,
    const float* __restrict__ bias, const float* __restrict__ res,
    void* __restrict__ Cv, int M, int N, int K)
{
    extern __shared__ char smc[];
    const uint32_t smb = smem_u32(smc);
    const int tid  = threadIdx.x;
    const int wid  = tid >> 5;
    const int lane = tid & 31;
    const int g = lane >> 2, c = lane & 3;
    const int wy = wid & 3, wx = wid >> 2;   // warp tile: rows wy*32+, cols wx*64+
    const int m0 = blockIdx.y * 128;
    const int n0 = blockIdx.x * 128;
    const int nch = K >> 6;

    // cp.async: per chunk, A 4 x 16B, B 4 x 16B per thread (8 thr/row)
    const int lr = tid >> 3, lj = tid & 7;           // row 0..31 base, 16B col
    const __half* asrc0 = A + (size_t)(m0 + lr) * K + lj * 8;
    const __half* bsrc0 = B + (size_t)(n0 + lr) * K + lj * 8;
    const uint32_t adst0 = (uint32_t)lr * ROWB + (uint32_t)lj * 16u;
    const uint32_t bdst0 = ATILE_B + adst0;
    const size_t rstep = (size_t)32 * K;             // 32 rows per i

    #pragma unroll
    for (int p = 0; p < NST - 1; p++) {
        uint32_t sb = smb + p * ST_BYTE;
        #pragma unroll
        for (int i = 0; i < 4; i++) {
            asm volatile("cp.async.cg.shared.global [%0], [%1], 16;"
                :: "r"(sb + adst0 + i*4608u), "l"(asrc0 + i*rstep + p*64));
            asm volatile("cp.async.cg.shared.global [%0], [%1], 16;"
                :: "r"(sb + bdst0 + i*4608u), "l"(bsrc0 + i*rstep + p*64));
        }
        asm volatile("cp.async.commit_group;");
    }

    float acc[2][8][4] = {};
    const uint32_t lrow  = (uint32_t)(lane & 15);
    const uint32_t lhalf = (uint32_t)(lane >> 4);

    for (int ch = 0; ch < nch; ch++) {
        asm volatile("cp.async.wait_group %0;" :: "n"(NST - 2));
        __syncthreads();

        int ch2 = ch + NST - 1;
        if (ch2 < nch) {
            uint32_t sb = smb + (uint32_t)(ch2 % NST) * ST_BYTE;
            #pragma unroll
            for (int i = 0; i < 4; i++) {
                asm volatile("cp.async.cg.shared.global [%0], [%1], 16;"
                    :: "r"(sb + adst0 + i*4608u), "l"(asrc0 + i*rstep + ch2*64));
                asm volatile("cp.async.cg.shared.global [%0], [%1], 16;"
                    :: "r"(sb + bdst0 + i*4608u), "l"(bsrc0 + i*rstep + ch2*64));
            }
        }
        asm volatile("cp.async.commit_group;");

        const uint32_t stb   = smb + (uint32_t)(ch % NST) * ST_BYTE;
        const uint32_t abase = stb + (uint32_t)(wy * 32 + lrow) * ROWB + lhalf * 16u;
        const uint32_t bbase = stb + ATILE_B
                             + (uint32_t)(wx * 64 + lrow) * ROWB + lhalf * 16u;

        #pragma unroll
        for (int ks = 0; ks < 4; ks++) {       // 4 k16-steps = K-chunk 64
            uint32_t koff = (uint32_t)ks * 32u;
            uint32_t af[2][4], bf[8][2];
            #pragma unroll
            for (int mf = 0; mf < 2; mf++)
                ldsm_x4(af[mf], abase + (uint32_t)mf * (16u * ROWB) + koff);
            #pragma unroll
            for (int np = 0; np < 4; np++) {
                uint32_t q[4];
                ldsm_x4(q, bbase + (uint32_t)np * (16u * ROWB) + koff);
                bf[2*np][0]   = q[0]; bf[2*np][1]   = q[2];
                bf[2*np+1][0] = q[1]; bf[2*np+1][1] = q[3];
            }
            #pragma unroll
            for (int mf = 0; mf < 2; mf++)
                #pragma unroll
                for (int nf = 0; nf < 8; nf++)
                    mma_f16(acc[mf][nf], af[mf], bf[nf]);
        }
    }

    const int mbase = m0 + wy * 32;
    const int nbase = n0 + wx * 64;
    #pragma unroll
    for (int mf = 0; mf < 2; mf++) {
        int r0 = mbase + mf * 16 + g;
        #pragma unroll
        for (int nf = 0; nf < 8; nf++) {
            int col = nbase + nf * 8 + c * 2;
            float v0 = acc[mf][nf][0], v1 = acc[mf][nf][1];
            float v2 = acc[mf][nf][2], v3 = acc[mf][nf][3];
            if (EPI >= 1) {
                float b0 = bias[col], b1 = bias[col + 1];
                v0 += b0; v1 += b1; v2 += b0; v3 += b1;
            }
            if (EPI == 1) {
                float* C = (float*)Cv;
                float2 r01 = *(const float2*)(res + (size_t)r0 * N + col);
                float2 r23 = *(const float2*)(res + (size_t)(r0 + 8) * N + col);
                *(float2*)(C + (size_t)r0 * N + col)       = make_float2(v0 + r01.x, v1 + r01.y);
                *(float2*)(C + (size_t)(r0 + 8) * N + col) = make_float2(v2 + r23.x, v3 + r23.y);
            } else {
                if (EPI == 2) {
                    v0 = v0 * normcdff(v0);
                    v1 = v1 * normcdff(v1);
                    v2 = v2 * normcdff(v2);
                    v3 = v3 * normcdff(v3);
                }
                __half* C = (__half*)Cv;
                *(uint32_t*)(C + (size_t)r0 * N + col)       = h2u(__floats2half2_rn(v0, v1));
                *(uint32_t*)(C + (size_t)(r0 + 8) * N + col) = h2u(__floats2half2_rn(v2, v3));
            }
        }
    }
}

// ---------------- Flash attention, fp16 mma (unchanged from R7) ----------------
#define FH_STR 72
#define FH_QS  0
#define FH_KS  (64*FH_STR)
#define FH_VS  (FH_KS + 64*FH_STR)
#define FH_PW  (FH_VS + 64*FH_STR)
#define FH_END (FH_PW + 4*16*FH_STR)
#define FSM_TOT (FH_END*2 + 256)

__global__ void __launch_bounds__(128) flashm_k(
    const __half* __restrict__ qkv, const int* __restrict__ ids,
    __half* __restrict__ o)
{
    extern __shared__ char smc[];
    __half* smh = (__half*)smc;
    __half* Qs  = smh + FH_QS;
    __half* Ks  = smh + FH_KS;
    __half* Vst = smh + FH_VS;
    float*  mk  = (float*)(smc + FH_END*2);
    const uint32_t smb = smem_u32(smc);

    const int tid = threadIdx.x;
    const int wid = tid >> 5, lane = tid & 31;
    const int g = lane >> 2, c = lane & 3;
    const int qt = blockIdx.x, h = blockIdx.y, b = blockIdx.z;
    const int q0 = qt * 64;
    const size_t rstr = 3 * CD;

    for (int i = tid; i < 512; i += 128) {
        int r = i >> 3, j = i & 7;
        *(uint4*)(Qs + r * FH_STR + j * 8) =
            *(const uint4*)(qkv + (size_t)(b*CN + q0 + r) * rstr + h*64 + j*8);
    }

    float oa[8][4] = {};
    float m0 = -1e30f, m1 = -1e30f, l0 = 0.f, l1 = 0.f;

    const uint32_t lrow  = (uint32_t)(lane & 15);
    const uint32_t lhalf = (uint32_t)(lane >> 4);
    const uint32_t qbase = smb + (uint32_t)(wid*16 + lrow) * 144u + lhalf * 16u;
    const uint32_t kbase = smb + (uint32_t)(FH_KS*2) + lrow * 144u + lhalf * 16u;
    const uint32_t vbase = smb + (uint32_t)(FH_VS*2) + lrow * 144u + lhalf * 16u;
    const uint32_t pbase = smb + (uint32_t)(FH_PW*2) + (uint32_t)wid * (16u*144u)
                         + lrow * 144u + lhalf * 16u;
    __half* Pw = smh + FH_PW + wid * 16 * FH_STR;

    for (int kt = 0; kt < 16; kt++) {
        int k0 = kt * 64;
        __syncthreads();
        for (int i = tid; i < 512; i += 128) {
            int r = i >> 3, j = i & 7;
            const __half* gk = qkv + (size_t)(b*CN + k0 + r) * rstr + CD + h*64 + j*8;
            *(uint4*)(Ks + r * FH_STR + j * 8) = *(const uint4*)gk;
            uint4 vv = *(const uint4*)(gk + CD);
            const __half* vh = (const __half*)&vv;
            #pragma unroll
            for (int t = 0; t < 8; t++)
                Vst[(j*8 + t) * FH_STR + r] = vh[t];
        }
        if (tid < 64) mk[tid] = -1.25e8f * (float)ids[b*CN + k0 + tid];
        __syncthreads();

        float sa[8][4] = {};
        #pragma unroll
        for (int ks = 0; ks < 4; ks++) {
            uint32_t koff = (uint32_t)ks * 32u;
            uint32_t a[4];
            ldsm_x4(a, qbase + koff);
            #pragma unroll
            for (int np = 0; np < 4; np++) {
                uint32_t q[4];
                ldsm_x4(q, kbase + (uint32_t)np * (16u*144u) + koff);
                uint32_t b0[2] = {q[0], q[2]}, b1[2] = {q[1], q[3]};
                mma_f16(sa[2*np],   a, b0);
                mma_f16(sa[2*np+1], a, b1);
            }
        }

        float rmax0 = -1e30f, rmax1 = -1e30f;
        #pragma unroll
        for (int nf = 0; nf < 8; nf++) {
            float mv0 = mk[nf*8 + 2*c], mv1 = mk[nf*8 + 2*c + 1];
            sa[nf][0] = sa[nf][0]*0.125f + mv0; sa[nf][1] = sa[nf][1]*0.125f + mv1;
            sa[nf][2] = sa[nf][2]*0.125f + mv0; sa[nf][3] = sa[nf][3]*0.125f + mv1;
            rmax0 = fmaxf(rmax0, fmaxf(sa[nf][0], sa[nf][1]));
            rmax1 = fmaxf(rmax1, fmaxf(sa[nf][2], sa[nf][3]));
        }
        rmax0 = fmaxf(rmax0, __shfl_xor_sync(0xffffffffu, rmax0, 1));
        rmax0 = fmaxf(rmax0, __shfl_xor_sync(0xffffffffu, rmax0, 2));
        rmax1 = fmaxf(rmax1, __shfl_xor_sync(0xffffffffu, rmax1, 1));
        rmax1 = fmaxf(rmax1, __shfl_xor_sync(0xffffffffu, rmax1, 2));
        float mn0 = fmaxf(m0, rmax0), mn1 = fmaxf(m1, rmax1);
        float al0 = __expf(m0 - mn0), al1 = __expf(m1 - mn1);
        m0 = mn0; m1 = mn1;
        float ps0 = 0.f, ps1 = 0.f;
        #pragma unroll
        for (int nf = 0; nf < 8; nf++) {
            float p0 = __expf(sa[nf][0] - mn0);
            float p1 = __expf(sa[nf][1] - mn0);
            float p2 = __expf(sa[nf][2] - mn1);
            float p3 = __expf(sa[nf][3] - mn1);
            ps0 += p0 + p1; ps1 += p2 + p3;
            *(uint32_t*)(Pw + g*FH_STR + nf*8 + 2*c)     = h2u(__floats2half2_rn(p0, p1));
            *(uint32_t*)(Pw + (g+8)*FH_STR + nf*8 + 2*c) = h2u(__floats2half2_rn(p2, p3));
        }
        ps0 += __shfl_xor_sync(0xffffffffu, ps0, 1);
        ps0 += __shfl_xor_sync(0xffffffffu, ps0, 2);
        ps1 += __shfl_xor_sync(0xffffffffu, ps1, 1);
        ps1 += __shfl_xor_sync(0xffffffffu, ps1, 2);
        l0 = l0 * al0 + ps0;
        l1 = l1 * al1 + ps1;
        #pragma unroll
        for (int nf = 0; nf < 8; nf++) {
            oa[nf][0] *= al0; oa[nf][1] *= al0;
            oa[nf][2] *= al1; oa[nf][3] *= al1;
        }
        __syncwarp();

        #pragma unroll
        for (int ks = 0; ks < 4; ks++) {
            uint32_t koff = (uint32_t)ks * 32u;
            uint32_t a[4];
            ldsm_x4(a, pbase + koff);
            #pragma unroll
            for (int np = 0; np < 4; np++) {
                uint32_t q[4];
                ldsm_x4(q, vbase + (uint32_t)np * (16u*144u) + koff);
                uint32_t b0[2] = {q[0], q[2]}, b1[2] = {q[1], q[3]};
                mma_f16(oa[2*np],   a, b0);
                mma_f16(oa[2*np+1], a, b1);
            }
        }
        __syncwarp();
    }

    float inv0 = 1.0f / l0, inv1 = 1.0f / l1;
    size_t r0 = (size_t)(b*CN + q0 + wid*16 + g) * CD + h*64;
    size_t r1 = (size_t)(b*CN + q0 + wid*16 + g + 8) * CD + h*64;
    #pragma unroll
    for (int nf = 0; nf < 8; nf++) {
        int col = nf*8 + 2*c;
        *(uint32_t*)(o + r0 + col) = h2u(__floats2half2_rn(oa[nf][0]*inv0, oa[nf][1]*inv0));
        *(uint32_t*)(o + r1 + col) = h2u(__floats2half2_rn(oa[nf][2]*inv1, oa[nf][3]*inv1));
    }
}

// ---------------- launch ----------------
extern "C" void kernel_launch(void* const* d_in, const int* in_sizes, int n_in,
                              void* d_out, int out_size)
{
    const float* x      = (const float*)d_in[0];
    const int*   ids    = (const int*)  d_in[1];
    const float* n1w    = (const float*)d_in[2];
    const float* n1b    = (const float*)d_in[3];
    const float* pin_w  = (const float*)d_in[4];
    const float* pout_w = (const float*)d_in[5];
    const float* pout_b = (const float*)d_in[6];
    const float* n2w    = (const float*)d_in[7];
    const float* n2b    = (const float*)d_in[8];
    const float* l1w    = (const float*)d_in[9];
    const float* l1b    = (const float*)d_in[10];
    const float* l2w    = (const float*)d_in[11];
    const float* l2b    = (const float*)d_in[12];
    float* out = (float*)d_out;

    __half *xnh, *qkvh, *aoh, *x2h, *hhh, *wqh, *woh, *w1h, *w2h;
    float *xnf, *x1f, *x2f;
    cudaGetSymbolAddress((void**)&xnh,  g_xn_h);
    cudaGetSymbolAddress((void**)&xnf,  g_xn_f);
    cudaGetSymbolAddress((void**)&qkvh, g_qkv_h);
    cudaGetSymbolAddress((void**)&aoh,  g_ao_h);
    cudaGetSymbolAddress((void**)&x1f,  g_x1_f);
    cudaGetSymbolAddress((void**)&x2h,  g_x2_h);
    cudaGetSymbolAddress((void**)&x2f,  g_x2_f);
    cudaGetSymbolAddress((void**)&hhh,  g_h_h);
    cudaGetSymbolAddress((void**)&wqh,  g_wq_h);
    cudaGetSymbolAddress((void**)&woh,  g_wo_h);
    cudaGetSymbolAddress((void**)&w1h,  g_w1_h);
    cudaGetSymbolAddress((void**)&w2h,  g_w2_h);

    cudaFuncSetAttribute(flashm_k,    cudaFuncAttributeMaxDynamicSharedMemorySize, FSM_TOT);
    cudaFuncSetAttribute(gemm_mma<0>, cudaFuncAttributeMaxDynamicSharedMemorySize, GSMEM);
    cudaFuncSetAttribute(gemm_mma<1>, cudaFuncAttributeMaxDynamicSharedMemorySize, GSMEM);
    cudaFuncSetAttribute(gemm_mma<2>, cudaFuncAttributeMaxDynamicSharedMemorySize, GSMEM);

    // 0) weights -> fp16
    round_f16_k<<<(3*CD*CD/4 + 255)/256, 256>>>((const float4*)pin_w,  (uint2*)wqh, 3*CD*CD/4);
    round_f16_k<<<(CD*CD/4   + 255)/256, 256>>>((const float4*)pout_w, (uint2*)woh, CD*CD/4);
    round_f16_k<<<(CFF*CD/4  + 255)/256, 256>>>((const float4*)l1w,    (uint2*)w1h, CFF*CD/4);
    round_f16_k<<<(CD*CFF/4  + 255)/256, 256>>>((const float4*)l2w,    (uint2*)w2h, CD*CFF/4);

    // 1) xn = LN1(x)
    layernorm_k<<<NTOK, 256>>>(x, n1w, n1b, xnh, xnf);
    // 2) qkv = xn @ Wq^T  (fp16 out)
    gemm_mma<0><<<dim3(3*CD/128, NTOK/128), 256, GSMEM>>>(xnh, wqh, nullptr, nullptr, qkvh, NTOK, 3*CD, CD);
    // 3) flash attention -> ao (fp16)
    flashm_k<<<dim3(CN/64, CH, CB), 128, FSM_TOT>>>(qkvh, ids, aoh);
    // 4) x1 = ao @ Wo^T + bout + xn  (fp32 out)
    gemm_mma<1><<<dim3(CD/128, NTOK/128), 256, GSMEM>>>(aoh, woh, pout_b, xnf, x1f, NTOK, CD, CD);
    // 5) x2 = LN2(x1)
    layernorm_k<<<NTOK, 256>>>(x1f, n2w, n2b, x2h, x2f);
    // 6) h = gelu(x2 @ W1^T + b1)  (fp16 out)
    gemm_mma<2><<<dim3(CFF/128, NTOK/128), 256, GSMEM>>>(x2h, w1h, l1b, nullptr, hhh, NTOK, CFF, CD);
    // 7) out = h @ W2^T + b2 + x2  (fp32 out)
    gemm_mma<1><<<dim3(CD/128, NTOK/128), 256, GSMEM>>>(hhh, w2h, l2b, x2f, out, NTOK, CD, CFF);
}

// round 9
// speedup vs baseline: 2.0734x; 1.0951x over previous
#include <cuda_runtime.h>
#include <cuda_fp16.h>
#include <math.h>
#include <stdint.h>

#define CD   1024
#define CH   16
#define CFF  4096
#define CB   8
#define CN   1024
#define NTOK (CB*CN)   // 8192

// ---------------- scratch (no allocations allowed) ----------------
__device__ __half g_xn_h [NTOK*CD];
__device__ float  g_xn_f [NTOK*CD];
__device__ __half g_qkv_h[NTOK*3*CD];
__device__ __half g_ao_h [NTOK*CD];
__device__ float  g_x1_f [NTOK*CD];
__device__ __half g_x2_h [NTOK*CD];
__device__ float  g_x2_f [NTOK*CD];
__device__ __half g_h_h  [NTOK*CFF];
__device__ __half g_wq_h [3*CD*CD];
__device__ __half g_wo_h [CD*CD];
__device__ __half g_w1_h [CFF*CD];
__device__ __half g_w2_h [CD*CFF];

// ---------------- helpers ----------------
__device__ __forceinline__ uint32_t smem_u32(const void* p) {
    uint32_t a;
    asm("{ .reg .u64 t; cvta.to.shared.u64 t, %1; cvt.u32.u64 %0, t; }" : "=r"(a) : "l"(p));
    return a;
}
__device__ __forceinline__ void mma_f16(float* d, const uint32_t* a, const uint32_t* b) {
    asm volatile(
        "mma.sync.aligned.m16n8k16.row.col.f32.f16.f16.f32 "
        "{%0,%1,%2,%3},{%4,%5,%6,%7},{%8,%9},{%0,%1,%2,%3};"
        : "+f"(d[0]), "+f"(d[1]), "+f"(d[2]), "+f"(d[3])
        : "r"(a[0]), "r"(a[1]), "r"(a[2]), "r"(a[3]), "r"(b[0]), "r"(b[1]));
}
__device__ __forceinline__ void ldsm_x4(uint32_t* r, uint32_t addr) {
    asm volatile("ldmatrix.sync.aligned.m8n8.x4.shared.b16 {%0,%1,%2,%3}, [%4];"
        : "=r"(r[0]), "=r"(r[1]), "=r"(r[2]), "=r"(r[3]) : "r"(addr));
}
__device__ __forceinline__ void ldsm_x4_t(uint32_t* r, uint32_t addr) {
    asm volatile("ldmatrix.sync.aligned.m8n8.x4.trans.shared.b16 {%0,%1,%2,%3}, [%4];"
        : "=r"(r[0]), "=r"(r[1]), "=r"(r[2]), "=r"(r[3]) : "r"(addr));
}
__device__ __forceinline__ uint32_t h2u(__half2 h) { return *(uint32_t*)&h; }

// ---------------- fp16 rounding copy (weights) ----------------
__global__ void round_f16_k(const float4* __restrict__ src, uint2* __restrict__ dst, int n4) {
    int i = blockIdx.x * blockDim.x + threadIdx.x;
    if (i < n4) {
        float4 v = src[i];
        uint2 o;
        o.x = h2u(__floats2half2_rn(v.x, v.y));
        o.y = h2u(__floats2half2_rn(v.z, v.w));
        dst[i] = o;
    }
}

// ---------------- LayerNorm: fp16 + fp32 outputs ----------------
__global__ void __launch_bounds__(256) layernorm_k(
    const float* __restrict__ x, const float* __restrict__ w,
    const float* __restrict__ b, __half* __restrict__ yh, float* __restrict__ yf)
{
    int row = blockIdx.x;
    int tid = threadIdx.x;
    const float4* xr = (const float4*)(x + (size_t)row * CD);
    float4 xv = xr[tid];
    float s  = xv.x + xv.y + xv.z + xv.w;
    float ss = xv.x*xv.x + xv.y*xv.y + xv.z*xv.z + xv.w*xv.w;
    #pragma unroll
    for (int o = 16; o; o >>= 1) {
        s  += __shfl_xor_sync(0xffffffffu, s,  o);
        ss += __shfl_xor_sync(0xffffffffu, ss, o);
    }
    __shared__ float sm1[8], sm2[8];
    if ((tid & 31) == 0) { sm1[tid >> 5] = s; sm2[tid >> 5] = ss; }
    __syncthreads();
    float ts = 0.f, tss = 0.f;
    #pragma unroll
    for (int i = 0; i < 8; i++) { ts += sm1[i]; tss += sm2[i]; }
    float mu   = ts * (1.0f / CD);
    float var  = tss * (1.0f / CD) - mu * mu;
    float rstd = rsqrtf(var + 1e-5f);
    float4 wv = ((const float4*)w)[tid];
    float4 bv = ((const float4*)b)[tid];
    float4 ov;
    ov.x = (xv.x - mu) * rstd * wv.x + bv.x;
    ov.y = (xv.y - mu) * rstd * wv.y + bv.y;
    ov.z = (xv.z - mu) * rstd * wv.z + bv.z;
    ov.w = (xv.w - mu) * rstd * wv.w + bv.w;
    ((float4*)(yf + (size_t)row * CD))[tid] = ov;
    uint2 oh;
    oh.x = h2u(__floats2half2_rn(ov.x, ov.y));
    oh.y = h2u(__floats2half2_rn(ov.z, ov.w));
    ((uint2*)(yh + (size_t)row * CD))[tid] = oh;
}

// ---------------- fp16 mma.sync NT GEMM, 2 CTAs/SM (R8, unchanged) ----------------
#define NST     3
#define ROWB    144u
#define ATILE_B 18432u
#define ST_BYTE (2u*ATILE_B)
#define GSMEM   (NST*ST_BYTE)          // 110592

template<int EPI>
__global__ void __launch_bounds__(256, 2) gemm_mma(
    const __half* __restrict__ A, const __half* __restrict__ B,
    const float* __restrict__ bias, const float* __restrict__ res,
    void* __restrict__ Cv, int M, int N, int K)
{
    extern __shared__ char smc[];
    const uint32_t smb = smem_u32(smc);
    const int tid  = threadIdx.x;
    const int wid  = tid >> 5;
    const int lane = tid & 31;
    const int g = lane >> 2, c = lane & 3;
    const int wy = wid & 3, wx = wid >> 2;
    const int m0 = blockIdx.y * 128;
    const int n0 = blockIdx.x * 128;
    const int nch = K >> 6;

    const int lr = tid >> 3, lj = tid & 7;
    const __half* asrc0 = A + (size_t)(m0 + lr) * K + lj * 8;
    const __half* bsrc0 = B + (size_t)(n0 + lr) * K + lj * 8;
    const uint32_t adst0 = (uint32_t)lr * ROWB + (uint32_t)lj * 16u;
    const uint32_t bdst0 = ATILE_B + adst0;
    const size_t rstep = (size_t)32 * K;

    #pragma unroll
    for (int p = 0; p < NST - 1; p++) {
        uint32_t sb = smb + p * ST_BYTE;
        #pragma unroll
        for (int i = 0; i < 4; i++) {
            asm volatile("cp.async.cg.shared.global [%0], [%1], 16;"
                :: "r"(sb + adst0 + i*4608u), "l"(asrc0 + i*rstep + p*64));
            asm volatile("cp.async.cg.shared.global [%0], [%1], 16;"
                :: "r"(sb + bdst0 + i*4608u), "l"(bsrc0 + i*rstep + p*64));
        }
        asm volatile("cp.async.commit_group;");
    }

    float acc[2][8][4] = {};
    const uint32_t lrow  = (uint32_t)(lane & 15);
    const uint32_t lhalf = (uint32_t)(lane >> 4);

    for (int ch = 0; ch < nch; ch++) {
        asm volatile("cp.async.wait_group %0;" :: "n"(NST - 2));
        __syncthreads();

        int ch2 = ch + NST - 1;
        if (ch2 < nch) {
            uint32_t sb = smb + (uint32_t)(ch2 % NST) * ST_BYTE;
            #pragma unroll
            for (int i = 0; i < 4; i++) {
                asm volatile("cp.async.cg.shared.global [%0], [%1], 16;"
                    :: "r"(sb + adst0 + i*4608u), "l"(asrc0 + i*rstep + ch2*64));
                asm volatile("cp.async.cg.shared.global [%0], [%1], 16;"
                    :: "r"(sb + bdst0 + i*4608u), "l"(bsrc0 + i*rstep + ch2*64));
            }
        }
        asm volatile("cp.async.commit_group;");

        const uint32_t stb   = smb + (uint32_t)(ch % NST) * ST_BYTE;
        const uint32_t abase = stb + (uint32_t)(wy * 32 + lrow) * ROWB + lhalf * 16u;
        const uint32_t bbase = stb + ATILE_B
                             + (uint32_t)(wx * 64 + lrow) * ROWB + lhalf * 16u;

        #pragma unroll
        for (int ks = 0; ks < 4; ks++) {
            uint32_t koff = (uint32_t)ks * 32u;
            uint32_t af[2][4], bf[8][2];
            #pragma unroll
            for (int mf = 0; mf < 2; mf++)
                ldsm_x4(af[mf], abase + (uint32_t)mf * (16u * ROWB) + koff);
            #pragma unroll
            for (int np = 0; np < 4; np++) {
                uint32_t q[4];
                ldsm_x4(q, bbase + (uint32_t)np * (16u * ROWB) + koff);
                bf[2*np][0]   = q[0]; bf[2*np][1]   = q[2];
                bf[2*np+1][0] = q[1]; bf[2*np+1][1] = q[3];
            }
            #pragma unroll
            for (int mf = 0; mf < 2; mf++)
                #pragma unroll
                for (int nf = 0; nf < 8; nf++)
                    mma_f16(acc[mf][nf], af[mf], bf[nf]);
        }
    }

    const int mbase = m0 + wy * 32;
    const int nbase = n0 + wx * 64;
    #pragma unroll
    for (int mf = 0; mf < 2; mf++) {
        int r0 = mbase + mf * 16 + g;
        #pragma unroll
        for (int nf = 0; nf < 8; nf++) {
            int col = nbase + nf * 8 + c * 2;
            float v0 = acc[mf][nf][0], v1 = acc[mf][nf][1];
            float v2 = acc[mf][nf][2], v3 = acc[mf][nf][3];
            if (EPI >= 1) {
                float b0 = bias[col], b1 = bias[col + 1];
                v0 += b0; v1 += b1; v2 += b0; v3 += b1;
            }
            if (EPI == 1) {
                float* C = (float*)Cv;
                float2 r01 = *(const float2*)(res + (size_t)r0 * N + col);
                float2 r23 = *(const float2*)(res + (size_t)(r0 + 8) * N + col);
                *(float2*)(C + (size_t)r0 * N + col)       = make_float2(v0 + r01.x, v1 + r01.y);
                *(float2*)(C + (size_t)(r0 + 8) * N + col) = make_float2(v2 + r23.x, v3 + r23.y);
            } else {
                if (EPI == 2) {
                    v0 = v0 * normcdff(v0);
                    v1 = v1 * normcdff(v1);
                    v2 = v2 * normcdff(v2);
                    v3 = v3 * normcdff(v3);
                }
                __half* C = (__half*)Cv;
                *(uint32_t*)(C + (size_t)r0 * N + col)       = h2u(__floats2half2_rn(v0, v1));
                *(uint32_t*)(C + (size_t)(r0 + 8) * N + col) = h2u(__floats2half2_rn(v2, v3));
            }
        }
    }
}

// ---------------- Flash attention, fp16 mma, q-tile 128, trans-V ----------------
// Block = (b, h, 128-q-tile), 256 threads = 8 warps, warp owns 16 q rows.
// smem halves (stride 72/row = 144B): Qs[128][72], Ks[64][72], Vs[64][72] (row-major),
// Pw[8][16][72], mask float[64].
#define FH_STR 72
#define FH_QS  0
#define FH_KS  (128*FH_STR)                 // 9216
#define FH_VS  (FH_KS + 64*FH_STR)          // 13824
#define FH_PW  (FH_VS + 64*FH_STR)          // 18432
#define FH_END (FH_PW + 8*16*FH_STR)        // 27648 halves
#define FSM_TOT (FH_END*2 + 256)            // 55552 B

__global__ void __launch_bounds__(256) flashm_k(
    const __half* __restrict__ qkv, const int* __restrict__ ids,
    __half* __restrict__ o)
{
    extern __shared__ char smc[];
    __half* smh = (__half*)smc;
    __half* Qs  = smh + FH_QS;
    __half* Ks  = smh + FH_KS;
    __half* Vs  = smh + FH_VS;
    float*  mk  = (float*)(smc + FH_END*2);
    const uint32_t smb = smem_u32(smc);

    const int tid = threadIdx.x;
    const int wid = tid >> 5, lane = tid & 31;
    const int g = lane >> 2, c = lane & 3;
    const int qt = blockIdx.x, h = blockIdx.y, b = blockIdx.z;
    const int q0 = qt * 128;
    const size_t rstr = 3 * CD;

    // load Q tile (128 rows)
    for (int i = tid; i < 1024; i += 256) {
        int r = i >> 3, j = i & 7;
        *(uint4*)(Qs + r * FH_STR + j * 8) =
            *(const uint4*)(qkv + (size_t)(b*CN + q0 + r) * rstr + h*64 + j*8);
    }

    float oa[8][4] = {};
    float m0 = -1e30f, m1 = -1e30f, l0 = 0.f, l1 = 0.f;

    const uint32_t lrow  = (uint32_t)(lane & 15);
    const uint32_t lhalf = (uint32_t)(lane >> 4);
    const uint32_t qbase = smb + (uint32_t)(wid*16 + lrow) * 144u + lhalf * 16u;
    const uint32_t kbase = smb + (uint32_t)(FH_KS*2) + lrow * 144u + lhalf * 16u;
    const uint32_t vbase = smb + (uint32_t)(FH_VS*2) + lrow * 144u + lhalf * 16u;
    const uint32_t pbase = smb + (uint32_t)(FH_PW*2) + (uint32_t)wid * (16u*144u)
                         + lrow * 144u + lhalf * 16u;
    __half* Pw = smh + FH_PW + wid * 16 * FH_STR;

    for (int kt = 0; kt < 16; kt++) {
        int k0 = kt * 64;
        __syncthreads();
        // K + V tiles: straight row-major copies (V transposed by ldmatrix.trans)
        for (int i = tid; i < 512; i += 256) {
            int r = i >> 3, j = i & 7;
            const __half* gk = qkv + (size_t)(b*CN + k0 + r) * rstr + CD + h*64 + j*8;
            *(uint4*)(Ks + r * FH_STR + j * 8) = *(const uint4*)gk;
            *(uint4*)(Vs + r * FH_STR + j * 8) = *(const uint4*)(gk + CD);
        }
        if (tid < 64) mk[tid] = -1.25e8f * (float)ids[b*CN + k0 + tid];
        __syncthreads();

        // ---- S = Q @ K^T ----
        float sa[8][4] = {};
        #pragma unroll
        for (int ks = 0; ks < 4; ks++) {
            uint32_t koff = (uint32_t)ks * 32u;
            uint32_t a[4];
            ldsm_x4(a, qbase + koff);
            #pragma unroll
            for (int np = 0; np < 4; np++) {
                uint32_t q[4];
                ldsm_x4(q, kbase + (uint32_t)np * (16u*144u) + koff);
                uint32_t b0[2] = {q[0], q[2]}, b1[2] = {q[1], q[3]};
                mma_f16(sa[2*np],   a, b0);
                mma_f16(sa[2*np+1], a, b1);
            }
        }

        // ---- scale + mask + online softmax ----
        float rmax0 = -1e30f, rmax1 = -1e30f;
        #pragma unroll
        for (int nf = 0; nf < 8; nf++) {
            float mv0 = mk[nf*8 + 2*c], mv1 = mk[nf*8 + 2*c + 1];
            sa[nf][0] = sa[nf][0]*0.125f + mv0; sa[nf][1] = sa[nf][1]*0.125f + mv1;
            sa[nf][2] = sa[nf][2]*0.125f + mv0; sa[nf][3] = sa[nf][3]*0.125f + mv1;
            rmax0 = fmaxf(rmax0, fmaxf(sa[nf][0], sa[nf][1]));
            rmax1 = fmaxf(rmax1, fmaxf(sa[nf][2], sa[nf][3]));
        }
        rmax0 = fmaxf(rmax0, __shfl_xor_sync(0xffffffffu, rmax0, 1));
        rmax0 = fmaxf(rmax0, __shfl_xor_sync(0xffffffffu, rmax0, 2));
        rmax1 = fmaxf(rmax1, __shfl_xor_sync(0xffffffffu, rmax1, 1));
        rmax1 = fmaxf(rmax1, __shfl_xor_sync(0xffffffffu, rmax1, 2));
        float mn0 = fmaxf(m0, rmax0), mn1 = fmaxf(m1, rmax1);
        float al0 = __expf(m0 - mn0), al1 = __expf(m1 - mn1);
        m0 = mn0; m1 = mn1;
        float ps0 = 0.f, ps1 = 0.f;
        #pragma unroll
        for (int nf = 0; nf < 8; nf++) {
            float p0 = __expf(sa[nf][0] - mn0);
            float p1 = __expf(sa[nf][1] - mn0);
            float p2 = __expf(sa[nf][2] - mn1);
            float p3 = __expf(sa[nf][3] - mn1);
            ps0 += p0 + p1; ps1 += p2 + p3;
            *(uint32_t*)(Pw + g*FH_STR + nf*8 + 2*c)     = h2u(__floats2half2_rn(p0, p1));
            *(uint32_t*)(Pw + (g+8)*FH_STR + nf*8 + 2*c) = h2u(__floats2half2_rn(p2, p3));
        }
        ps0 += __shfl_xor_sync(0xffffffffu, ps0, 1);
        ps0 += __shfl_xor_sync(0xffffffffu, ps0, 2);
        ps1 += __shfl_xor_sync(0xffffffffu, ps1, 1);
        ps1 += __shfl_xor_sync(0xffffffffu, ps1, 2);
        l0 = l0 * al0 + ps0;
        l1 = l1 * al1 + ps1;
        #pragma unroll
        for (int nf = 0; nf < 8; nf++) {
            oa[nf][0] *= al0; oa[nf][1] *= al0;
            oa[nf][2] *= al1; oa[nf][3] *= al1;
        }
        __syncwarp();

        // ---- O += P @ V  (V row-major, fragments via ldmatrix.trans) ----
        #pragma unroll
        for (int ks = 0; ks < 4; ks++) {
            uint32_t a[4];
            ldsm_x4(a, pbase + (uint32_t)ks * 32u);
            #pragma unroll
            for (int np = 0; np < 4; np++) {
                uint32_t q[4];
                ldsm_x4_t(q, vbase + (uint32_t)ks * (16u*144u) + (uint32_t)np * 32u);
                uint32_t b0[2] = {q[0], q[1]}, b1[2] = {q[2], q[3]};
                mma_f16(oa[2*np],   a, b0);
                mma_f16(oa[2*np+1], a, b1);
            }
        }
        __syncwarp();
    }

    // ---- epilogue ----
    float inv0 = 1.0f / l0, inv1 = 1.0f / l1;
    size_t r0 = (size_t)(b*CN + q0 + wid*16 + g) * CD + h*64;
    size_t r1 = (size_t)(b*CN + q0 + wid*16 + g + 8) * CD + h*64;
    #pragma unroll
    for (int nf = 0; nf < 8; nf++) {
        int col = nf*8 + 2*c;
        *(uint32_t*)(o + r0 + col) = h2u(__floats2half2_rn(oa[nf][0]*inv0, oa[nf][1]*inv0));
        *(uint32_t*)(o + r1 + col) = h2u(__floats2half2_rn(oa[nf][2]*inv1, oa[nf][3]*inv1));
    }
}

// ---------------- launch ----------------
extern "C" void kernel_launch(void* const* d_in, const int* in_sizes, int n_in,
                              void* d_out, int out_size)
{
    const float* x      = (const float*)d_in[0];
    const int*   ids    = (const int*)  d_in[1];
    const float* n1w    = (const float*)d_in[2];
    const float* n1b    = (const float*)d_in[3];
    const float* pin_w  = (const float*)d_in[4];
    const float* pout_w = (const float*)d_in[5];
    const float* pout_b = (const float*)d_in[6];
    const float* n2w    = (const float*)d_in[7];
    const float* n2b    = (const float*)d_in[8];
    const float* l1w    = (const float*)d_in[9];
    const float* l1b    = (const float*)d_in[10];
    const float* l2w    = (const float*)d_in[11];
    const float* l2b    = (const float*)d_in[12];
    float* out = (float*)d_out;

    __half *xnh, *qkvh, *aoh, *x2h, *hhh, *wqh, *woh, *w1h, *w2h;
    float *xnf, *x1f, *x2f;
    cudaGetSymbolAddress((void**)&xnh,  g_xn_h);
    cudaGetSymbolAddress((void**)&xnf,  g_xn_f);
    cudaGetSymbolAddress((void**)&qkvh, g_qkv_h);
    cudaGetSymbolAddress((void**)&aoh,  g_ao_h);
    cudaGetSymbolAddress((void**)&x1f,  g_x1_f);
    cudaGetSymbolAddress((void**)&x2h,  g_x2_h);
    cudaGetSymbolAddress((void**)&x2f,  g_x2_f);
    cudaGetSymbolAddress((void**)&hhh,  g_h_h);
    cudaGetSymbolAddress((void**)&wqh,  g_wq_h);
    cudaGetSymbolAddress((void**)&woh,  g_wo_h);
    cudaGetSymbolAddress((void**)&w1h,  g_w1_h);
    cudaGetSymbolAddress((void**)&w2h,  g_w2_h);

    cudaFuncSetAttribute(flashm_k,    cudaFuncAttributeMaxDynamicSharedMemorySize, FSM_TOT);
    cudaFuncSetAttribute(gemm_mma<0>, cudaFuncAttributeMaxDynamicSharedMemorySize, GSMEM);
    cudaFuncSetAttribute(gemm_mma<1>, cudaFuncAttributeMaxDynamicSharedMemorySize, GSMEM);
    cudaFuncSetAttribute(gemm_mma<2>, cudaFuncAttributeMaxDynamicSharedMemorySize, GSMEM);

    // 0) weights -> fp16
    round_f16_k<<<(3*CD*CD/4 + 255)/256, 256>>>((const float4*)pin_w,  (uint2*)wqh, 3*CD*CD/4);
    round_f16_k<<<(CD*CD/4   + 255)/256, 256>>>((const float4*)pout_w, (uint2*)woh, CD*CD/4);
    round_f16_k<<<(CFF*CD/4  + 255)/256, 256>>>((const float4*)l1w,    (uint2*)w1h, CFF*CD/4);
    round_f16_k<<<(CD*CFF/4  + 255)/256, 256>>>((const float4*)l2w,    (uint2*)w2h, CD*CFF/4);

    // 1) xn = LN1(x)
    layernorm_k<<<NTOK, 256>>>(x, n1w, n1b, xnh, xnf);
    // 2) qkv = xn @ Wq^T  (fp16 out)
    gemm_mma<0><<<dim3(3*CD/128, NTOK/128), 256, GSMEM>>>(xnh, wqh, nullptr, nullptr, qkvh, NTOK, 3*CD, CD);
    // 3) flash attention -> ao (fp16)
    flashm_k<<<dim3(CN/128, CH, CB), 256, FSM_TOT>>>(qkvh, ids, aoh);
    // 4) x1 = ao @ Wo^T + bout + xn  (fp32 out)
    gemm_mma<1><<<dim3(CD/128, NTOK/128), 256, GSMEM>>>(aoh, woh, pout_b, xnf, x1f, NTOK, CD, CD);
    // 5) x2 = LN2(x1)
    layernorm_k<<<NTOK, 256>>>(x1f, n2w, n2b, x2h, x2f);
    // 6) h = gelu(x2 @ W1^T + b1)  (fp16 out)
    gemm_mma<2><<<dim3(CFF/128, NTOK/128), 256, GSMEM>>>(x2h, w1h, l1b, nullptr, hhh, NTOK, CFF, CD);
    // 7) out = h @ W2^T + b2 + x2  (fp32 out)
    gemm_mma<1><<<dim3(CD/128, NTOK/128), 256, GSMEM>>>(hhh, w2h, l2b, x2f, out, NTOK, CD, CFF);
}